// round 7
// baseline (speedup 1.0000x reference)
#include <cuda_runtime.h>
#include <cuda_fp16.h>
#include <math.h>
#include <stdint.h>

#define NB 64
#define NL 64
#define ND 512
#define TEMP1 4.0f
#define TEMP2 5.0f
#define TEMP3 10.0f
#define EPSV 1e-8f

// ---------------- scratch (__device__ globals; no allocation allowed) -------
__device__ float Gg[NB * NL * NL];
__device__ float w1g[NB * NL];
__device__ float simg[NB * NB];
// fp16 hi/lo splits, k-chunked + ldmatrix-swizzled: [kc(32)][row(4096)][16 halfs]
__device__ __align__(128) __half eh_g[32 * 4096 * 16];
__device__ __align__(128) __half el_g[32 * 4096 * 16];
__device__ __align__(128) __half sh_g[32 * 4096 * 16];
__device__ __align__(128) __half sl_g[32 * 4096 * 16];

// ---------------- PTX helpers (baseline ISA: sm_80/sm_90, no 'a' features) --
__device__ __forceinline__ uint32_t smem_u32(const void* p) {
    return (uint32_t)__cvta_generic_to_shared(p);
}
__device__ __forceinline__ void bulk_cp(uint32_t dst, const void* src, uint32_t bytes, uint32_t mbar) {
    asm volatile("cp.async.bulk.shared::cta.global.mbarrier::complete_tx::bytes [%0], [%1], %2, [%3];"
        :: "r"(dst), "l"(src), "r"(bytes), "r"(mbar) : "memory");
}
#define MBAR_INIT(a, n) asm volatile("mbarrier.init.shared.b64 [%0], %1;" :: "r"(a), "r"(n) : "memory")
#define MBAR_EXPECT_TX(a, tx) asm volatile("mbarrier.arrive.expect_tx.shared.b64 _, [%0], %1;" :: "r"(a), "r"(tx) : "memory")
__device__ __forceinline__ void mbar_wait(uint32_t addr, int phase) {
    asm volatile(
        "{\n\t.reg .pred P;\n\t"
        "W_%=:\n\t"
        "mbarrier.try_wait.parity.acquire.cta.shared::cta.b64 P, [%0], %1, 0x989680;\n\t"
        "@P bra.uni D_%=;\n\t"
        "bra.uni W_%=;\n\t"
        "D_%=:\n\t}"
        :: "r"(addr), "r"(phase) : "memory");
}
__device__ __forceinline__ void ldsm4(uint32_t* r, uint32_t a) {
    asm volatile("ldmatrix.sync.aligned.m8n8.x4.shared.b16 {%0,%1,%2,%3}, [%4];"
        : "=r"(r[0]), "=r"(r[1]), "=r"(r[2]), "=r"(r[3]) : "r"(a));
}
__device__ __forceinline__ void mma16816(float* d, const uint32_t* a, const uint32_t* b) {
    asm volatile(
        "mma.sync.aligned.m16n8k16.row.col.f32.f16.f16.f32 "
        "{%0,%1,%2,%3}, {%4,%5,%6,%7}, {%8,%9}, {%0,%1,%2,%3};"
        : "+f"(d[0]), "+f"(d[1]), "+f"(d[2]), "+f"(d[3])
        : "r"(a[0]), "r"(a[1]), "r"(a[2]), "r"(a[3]), "r"(b[0]), "r"(b[1]));
}

// ---------------------------------------------------------------------------
// convert: fp32 -> fp16 hi + lo, k-chunked layout with baked ldmatrix swizzle.
__global__ void __launch_bounds__(256) convert_kernel(const float4* __restrict__ ecg,
                                                      const float4* __restrict__ sent) {
    int n = blockIdx.x * 256 + threadIdx.x;     // 0..262143
    int kc = n >> 13;
    int r  = (n >> 1) & 4095;
    int s  = n & 1;
    int sw = s ^ ((r >> 2) & 1);
    size_t dst = (size_t)kc * 8192 + (size_t)r * 2 + sw;       // uint4 index
    size_t src = ((size_t)r * 512 + (size_t)kc * 16 + (size_t)s * 8) >> 2;  // float4 index

    float4 a0 = ecg[src], a1 = ecg[src + 1];
    uint4 h, l;
    {
        __half2 h2, l2;
        float2 f;
        f = make_float2(a0.x, a0.y); h2 = __float22half2_rn(f);
        l2 = __float22half2_rn(make_float2(f.x - __half2float(h2.x), f.y - __half2float(h2.y)));
        h.x = *(uint32_t*)&h2; l.x = *(uint32_t*)&l2;
        f = make_float2(a0.z, a0.w); h2 = __float22half2_rn(f);
        l2 = __float22half2_rn(make_float2(f.x - __half2float(h2.x), f.y - __half2float(h2.y)));
        h.y = *(uint32_t*)&h2; l.y = *(uint32_t*)&l2;
        f = make_float2(a1.x, a1.y); h2 = __float22half2_rn(f);
        l2 = __float22half2_rn(make_float2(f.x - __half2float(h2.x), f.y - __half2float(h2.y)));
        h.z = *(uint32_t*)&h2; l.z = *(uint32_t*)&l2;
        f = make_float2(a1.z, a1.w); h2 = __float22half2_rn(f);
        l2 = __float22half2_rn(make_float2(f.x - __half2float(h2.x), f.y - __half2float(h2.y)));
        h.w = *(uint32_t*)&h2; l.w = *(uint32_t*)&l2;
    }
    ((uint4*)eh_g)[dst] = h;
    ((uint4*)el_g)[dst] = l;

    float4 b0 = sent[src], b1 = sent[src + 1];
    {
        __half2 h2, l2;
        float2 f;
        f = make_float2(b0.x, b0.y); h2 = __float22half2_rn(f);
        l2 = __float22half2_rn(make_float2(f.x - __half2float(h2.x), f.y - __half2float(h2.y)));
        h.x = *(uint32_t*)&h2; l.x = *(uint32_t*)&l2;
        f = make_float2(b0.z, b0.w); h2 = __float22half2_rn(f);
        l2 = __float22half2_rn(make_float2(f.x - __half2float(h2.x), f.y - __half2float(h2.y)));
        h.y = *(uint32_t*)&h2; l.y = *(uint32_t*)&l2;
        f = make_float2(b1.x, b1.y); h2 = __float22half2_rn(f);
        l2 = __float22half2_rn(make_float2(f.x - __half2float(h2.x), f.y - __half2float(h2.y)));
        h.z = *(uint32_t*)&h2; l.z = *(uint32_t*)&l2;
        f = make_float2(b1.z, b1.w); h2 = __float22half2_rn(f);
        l2 = __float22half2_rn(make_float2(f.x - __half2float(h2.x), f.y - __half2float(h2.y)));
        h.w = *(uint32_t*)&h2; l.w = *(uint32_t*)&l2;
    }
    ((uint4*)sh_g)[dst] = h;
    ((uint4*)sl_g)[dst] = l;
}

// ---------------------------------------------------------------------------
__global__ void w1_kernel(const float* __restrict__ sent) {
    int row = blockIdx.x * 8 + (threadIdx.x >> 5);
    int lane = threadIdx.x & 31;
    const float* p = sent + (size_t)row * ND;
    float s = 0.f;
    #pragma unroll
    for (int d = lane; d < ND; d += 32) { float v = p[d]; s += v * v; }
    #pragma unroll
    for (int o = 16; o; o >>= 1) s += __shfl_xor_sync(0xffffffffu, s, o);
    if (lane == 0) w1g[row] = sqrtf(s);
}

// ---------------------------------------------------------------------------
__global__ void __launch_bounds__(256) gram_kernel(const float* __restrict__ ecg) {
    __shared__ float tile[64][68];
    int j = blockIdx.x;
    int tid = threadIdx.x;
    int tx = tid & 15, ty = tid >> 4;
    const float* E = ecg + (size_t)j * NL * ND;

    float acc[4][4] = {};
    for (int kc = 0; kc < ND; kc += 64) {
        __syncthreads();
        for (int n = tid; n < 64 * 64; n += 256) {
            int r = n >> 6, d = n & 63;
            tile[d][r] = E[r * ND + kc + d];
        }
        __syncthreads();
        #pragma unroll 8
        for (int d = 0; d < 64; d++) {
            float4 a = *(const float4*)&tile[d][ty * 4];
            float4 b = *(const float4*)&tile[d][tx * 4];
            acc[0][0] += a.x * b.x; acc[0][1] += a.x * b.y; acc[0][2] += a.x * b.z; acc[0][3] += a.x * b.w;
            acc[1][0] += a.y * b.x; acc[1][1] += a.y * b.y; acc[1][2] += a.y * b.z; acc[1][3] += a.y * b.w;
            acc[2][0] += a.z * b.x; acc[2][1] += a.z * b.y; acc[2][2] += a.z * b.z; acc[2][3] += a.z * b.w;
            acc[3][0] += a.w * b.x; acc[3][1] += a.w * b.y; acc[3][2] += a.w * b.z; acc[3][3] += a.w * b.w;
        }
    }
    float* Gj = Gg + (size_t)j * NL * NL;
    #pragma unroll
    for (int ss = 0; ss < 4; ss++)
        #pragma unroll
        for (int qq = 0; qq < 4; qq++)
            Gj[(ty * 4 + ss) * NL + tx * 4 + qq] = acc[ss][qq];
}

// ---------------------------------------------------------------------------
// pair_kernel: CTA = (bi, bj); 128 ecg rows x 128 sent rows. fp16x3 mma GEMM,
// depth-4 cp.async.bulk stage ring; S (fp32) overlays the stages post-GEMM.
#define STAGE 16384
#define SROW 133
#define SBYTES (128 * SROW * 4)                 // 68096 > 4*STAGE
#define DSMEM_BYTES (SBYTES + 2 * 16384)

__global__ void __launch_bounds__(256, 2) pair_kernel(float* __restrict__ out) {
    extern __shared__ char dsm[];
    __shared__ uint64_t full_mb[4];
    __shared__ float w12s[64];
    __shared__ float w2sqs[64];
    __shared__ float ssum;

    uint32_t base = smem_u32(dsm);              // stages 0..3 (and later S)
    float* S    = (float*)dsm;                  // 128 x 133 fp32, overlays stages
    float* bufG = (float*)(dsm + SBYTES);
    float* bufQ = (float*)(dsm + SBYTES + 16384);

    int tid = threadIdx.x;
    int wid = tid >> 5, lane = tid & 31;
    int bi = blockIdx.x, bj = blockIdx.y;
    int wm = wid & 1, wn = wid >> 1;

    const char* ehp = (const char*)eh_g;
    const char* elp = (const char*)el_g;
    const char* shp = (const char*)sh_g;
    const char* slp = (const char*)sl_g;
    size_t aoff = (size_t)bj * 4096;
    size_t boff = (size_t)bi * 4096;

    // ldmatrix lane offsets (swizzle baked in gmem: seg ^= (row>>2)&1, 32B rows)
    int q4 = lane >> 3;
    int ar = (lane & 7) + (q4 & 1) * 8;
    int as = q4 >> 1;
    uint32_t offA = (uint32_t)((wm * 64 + ar) * 32 + ((as ^ ((ar >> 2) & 1)) * 16));
    int br = (lane & 7) + ((q4 >> 1) & 1) * 8;
    int bs = q4 & 1;
    uint32_t offB = (uint32_t)((wn * 32 + br) * 32 + ((bs ^ ((br >> 2) & 1)) * 16));

    uint32_t mb[4];
    #pragma unroll
    for (int s = 0; s < 4; s++) mb[s] = smem_u32(&full_mb[s]);

    if (tid == 0) {
        #pragma unroll
        for (int s = 0; s < 4; s++) MBAR_INIT(mb[s], 1);
    }
    __syncthreads();

    auto fill = [&](int s, int kc) {
        uint32_t st = base + (uint32_t)s * STAGE;
        size_t blk = (size_t)kc * 131072;   // kc block = 4096 rows * 32B
        MBAR_EXPECT_TX(mb[s], STAGE);
        bulk_cp(st,          ehp + blk + aoff, 4096, mb[s]);
        bulk_cp(st + 4096,   elp + blk + aoff, 4096, mb[s]);
        bulk_cp(st + 8192,   shp + blk + boff, 4096, mb[s]);
        bulk_cp(st + 12288,  slp + blk + boff, 4096, mb[s]);
    };

    if (tid == 0) {
        #pragma unroll
        for (int s = 0; s < 4; s++) fill(s, s);
    }

    float acc[4][4][4] = {};

    for (int c = 0; c < 32; c++) {
        int s = c & 3;
        uint32_t st = base + (uint32_t)s * STAGE;
        mbar_wait(mb[s], (c >> 2) & 1);

        uint32_t af[4][4], al[4][4], bh[2][4], bl[2][4];
        ldsm4(bh[0], st + 8192 + offB);
        ldsm4(bh[1], st + 8192 + offB + 512);
        ldsm4(bl[0], st + 12288 + offB);
        ldsm4(bl[1], st + 12288 + offB + 512);
        #pragma unroll
        for (int f = 0; f < 4; f++) ldsm4(af[f], st + offA + f * 512);
        #pragma unroll
        for (int f = 0; f < 4; f++) ldsm4(al[f], st + 4096 + offA + f * 512);

        __syncthreads();   // all warps finished reading this stage
        if (tid == 0 && c + 4 < 32) fill(s, c + 4);

        #pragma unroll
        for (int f = 0; f < 4; f++)
            #pragma unroll
            for (int g = 0; g < 4; g++) {
                mma16816(acc[f][g], af[f], &bh[g >> 1][(g & 1) * 2]);
                mma16816(acc[f][g], af[f], &bl[g >> 1][(g & 1) * 2]);
                mma16816(acc[f][g], al[f], &bh[g >> 1][(g & 1) * 2]);
            }
    }
    __syncthreads();   // everyone past the last ldsm before S overwrites stages

    // ---- write S (scores, fp32) to smem (overlays stage memory)
    {
        int r0 = lane >> 2, c0 = (lane & 3) * 2;
        #pragma unroll
        for (int f = 0; f < 4; f++)
            #pragma unroll
            for (int g = 0; g < 4; g++) {
                float* p = S + (size_t)(wm * 64 + f * 16 + r0) * SROW + wn * 32 + g * 8 + c0;
                p[0] = acc[f][g][0];
                p[1] = acc[f][g][1];
                p[8 * SROW] = acc[f][g][2];
                p[8 * SROW + 1] = acc[f][g][3];
            }
    }
    __syncthreads();

    // ---- epilogue: 4 (i,j) pairs
    int tx = tid & 15, ty = tid >> 4;
    for (int p = 0; p < 4; p++) {
        int jh = p >> 1, ih = p & 1;
        int i = 2 * bi + ih;
        int j = 2 * bj + jh;
        const float* Sp = S + (size_t)(64 * jh) * SROW + 64 * ih;  // S[s][q]

        if (ih == 0) {
            const float* Gj = Gg + (size_t)j * NL * NL;
            for (int n = tid; n < 64 * 64; n += 256) bufG[n] = Gj[n];
        }
        if (tid < 64) w2sqs[tid] = 0.f;
        if (tid == 0) ssum = 0.f;
        __syncthreads();

        // softmax 1 over q (per row s): attn1[s][q] -> bufQ
        {
            int g = tid >> 2, l = tid & 3;
            float v[16];
            float mx = -1e30f;
            #pragma unroll
            for (int m = 0; m < 16; m++) { v[m] = Sp[g * SROW + l * 16 + m]; mx = fmaxf(mx, v[m]); }
            mx = fmaxf(mx, __shfl_xor_sync(0xffffffffu, mx, 1));
            mx = fmaxf(mx, __shfl_xor_sync(0xffffffffu, mx, 2));
            float sm = 0.f;
            #pragma unroll
            for (int m = 0; m < 16; m++) { v[m] = __expf(v[m] - mx); sm += v[m]; }
            sm += __shfl_xor_sync(0xffffffffu, sm, 1);
            sm += __shfl_xor_sync(0xffffffffu, sm, 2);
            float inv = 1.f / sm;
            #pragma unroll
            for (int m = 0; m < 16; m++) bufQ[g * 64 + l * 16 + m] = v[m] * inv;
        }
        __syncthreads();

        // softmax 2 over s (transposed): A[q][s] -> bufQ, plus w12
        float e[16];
        float invs;
        {
            int q = tid >> 2, l = tid & 3;
            float mx = -1e30f;
            #pragma unroll
            for (int m = 0; m < 16; m++) { e[m] = TEMP1 * bufQ[(l * 16 + m) * 64 + q]; mx = fmaxf(mx, e[m]); }
            mx = fmaxf(mx, __shfl_xor_sync(0xffffffffu, mx, 1));
            mx = fmaxf(mx, __shfl_xor_sync(0xffffffffu, mx, 2));
            float sm = 0.f;
            #pragma unroll
            for (int m = 0; m < 16; m++) { e[m] = __expf(e[m] - mx); sm += e[m]; }
            sm += __shfl_xor_sync(0xffffffffu, sm, 1);
            sm += __shfl_xor_sync(0xffffffffu, sm, 2);
            invs = 1.f / sm;
        }
        __syncthreads();
        {
            int q = tid >> 2, l = tid & 3;
            float w12p = 0.f;
            #pragma unroll
            for (int m = 0; m < 16; m++) {
                int s = l * 16 + m;
                float a = e[m] * invs;
                bufQ[q * 64 + s] = a;
                w12p += a * Sp[s * SROW + q];
            }
            w12p += __shfl_xor_sync(0xffffffffu, w12p, 1);
            w12p += __shfl_xor_sync(0xffffffffu, w12p, 2);
            if (l == 0) w12s[q] = w12p;
        }
        __syncthreads();

        // w2sq[q] = diag(A G A^T)
        {
            float acc2[4][4] = {};
            #pragma unroll 8
            for (int u = 0; u < 64; u++) {
                float a0 = bufQ[(ty * 4 + 0) * 64 + u];
                float a1 = bufQ[(ty * 4 + 1) * 64 + u];
                float a2 = bufQ[(ty * 4 + 2) * 64 + u];
                float a3 = bufQ[(ty * 4 + 3) * 64 + u];
                float4 b = *(const float4*)&bufG[u * 64 + tx * 4];
                acc2[0][0] += a0 * b.x; acc2[0][1] += a0 * b.y; acc2[0][2] += a0 * b.z; acc2[0][3] += a0 * b.w;
                acc2[1][0] += a1 * b.x; acc2[1][1] += a1 * b.y; acc2[1][2] += a1 * b.z; acc2[1][3] += a1 * b.w;
                acc2[2][0] += a2 * b.x; acc2[2][1] += a2 * b.y; acc2[2][2] += a2 * b.z; acc2[2][3] += a2 * b.w;
                acc2[3][0] += a3 * b.x; acc2[3][1] += a3 * b.y; acc2[3][2] += a3 * b.z; acc2[3][3] += a3 * b.w;
            }
            #pragma unroll
            for (int ss = 0; ss < 4; ss++) {
                int qq0 = ty * 4 + ss;
                float pv = 0.f;
                #pragma unroll
                for (int qq = 0; qq < 4; qq++) pv += acc2[ss][qq] * bufQ[qq0 * 64 + tx * 4 + qq];
                atomicAdd(&w2sqs[qq0], pv);
            }
        }
        __syncthreads();

        if (tid < 64) {
            int qv = tid;
            float w2 = sqrtf(w2sqs[qv]);
            float cosv = w12s[qv] / fmaxf(w1g[i * NL + qv] * w2, EPSV);
            atomicAdd(&ssum, __expf(TEMP2 * cosv));
        }
        __syncthreads();
        if (tid == 0) simg[j * NB + i] = TEMP3 * logf(ssum);

        if (i == j) {
            float* om = out + 1 + (size_t)i * NL * NL;
            for (int n = tid; n < 64 * 64; n += 256) om[n] = bufQ[n];
        }
        __syncthreads();
    }
}

// ---------------------------------------------------------------------------
__global__ void __launch_bounds__(256) loss_kernel(float* __restrict__ out) {
    __shared__ float sm[64][65];
    __shared__ float acc;
    int t = threadIdx.x;
    if (t == 0) acc = 0.f;
    for (int n = t; n < 4096; n += 256) sm[n >> 6][n & 63] = simg[n];
    __syncthreads();
    int g = t >> 2, l = t & 3;
    float mx = -1e30f;
    #pragma unroll
    for (int m = 0; m < 16; m++) mx = fmaxf(mx, sm[g][l * 16 + m]);
    mx = fmaxf(mx, __shfl_xor_sync(0xffffffffu, mx, 1));
    mx = fmaxf(mx, __shfl_xor_sync(0xffffffffu, mx, 2));
    float s = 0.f;
    #pragma unroll
    for (int m = 0; m < 16; m++) s += expf(sm[g][l * 16 + m] - mx);
    s += __shfl_xor_sync(0xffffffffu, s, 1);
    s += __shfl_xor_sync(0xffffffffu, s, 2);
    float lp0 = sm[g][g] - mx - logf(s);

    float mc = -1e30f;
    #pragma unroll
    for (int m = 0; m < 16; m++) mc = fmaxf(mc, sm[l * 16 + m][g]);
    mc = fmaxf(mc, __shfl_xor_sync(0xffffffffu, mc, 1));
    mc = fmaxf(mc, __shfl_xor_sync(0xffffffffu, mc, 2));
    float sc = 0.f;
    #pragma unroll
    for (int m = 0; m < 16; m++) sc += expf(sm[l * 16 + m][g] - mc);
    sc += __shfl_xor_sync(0xffffffffu, sc, 1);
    sc += __shfl_xor_sync(0xffffffffu, sc, 2);
    float lp1 = sm[g][g] - mc - logf(sc);

    if (l == 0) atomicAdd(&acc, lp0 + lp1);
    __syncthreads();
    if (t == 0) out[0] = -acc / (2.0f * (float)NB);
}

// ---------------------------------------------------------------------------
extern "C" void kernel_launch(void* const* d_in, const int* in_sizes, int n_in,
                              void* d_out, int out_size) {
    const float* ecg = (const float*)d_in[0];
    const float* sent = (const float*)d_in[1];
    float* out = (float*)d_out;

    cudaFuncSetAttribute(pair_kernel, cudaFuncAttributeMaxDynamicSharedMemorySize, DSMEM_BYTES);

    convert_kernel<<<1024, 256>>>((const float4*)ecg, (const float4*)sent);
    w1_kernel<<<NB * NL / 8, 256>>>(sent);
    gram_kernel<<<NB, 256>>>(ecg);
    dim3 grid(32, 32);
    pair_kernel<<<grid, 256, DSMEM_BYTES>>>(out);
    loss_kernel<<<1, 256>>>(out);
}

// round 8
// speedup vs baseline: 1.2184x; 1.2184x over previous
#include <cuda_runtime.h>
#include <cuda_fp16.h>
#include <math.h>
#include <stdint.h>

#define NB 64
#define NL 64
#define ND 512
#define TEMP1 4.0f
#define TEMP2 5.0f
#define TEMP3 10.0f
#define EPSV 1e-8f

// ---------------- scratch (__device__ globals; no allocation allowed) -------
__device__ float w1g[NB * NL];
__device__ float simg[NB * NB];
__device__ __half Ghg[NB * 64 * 64];   // Gram hi fp16, row-major per j
__device__ __half Glg[NB * 64 * 64];   // Gram lo residual
// fp16 hi/lo splits, k-chunked + ldmatrix-swizzled: [kc(32)][row(4096)][16 halfs]
__device__ __align__(128) __half eh_g[32 * 4096 * 16];
__device__ __align__(128) __half el_g[32 * 4096 * 16];
__device__ __align__(128) __half sh_g[32 * 4096 * 16];
__device__ __align__(128) __half sl_g[32 * 4096 * 16];

// ---------------- PTX helpers (baseline ISA: sm_80/sm_90, no 'a' features) --
__device__ __forceinline__ uint32_t smem_u32(const void* p) {
    return (uint32_t)__cvta_generic_to_shared(p);
}
__device__ __forceinline__ void bulk_cp(uint32_t dst, const void* src, uint32_t bytes, uint32_t mbar) {
    asm volatile("cp.async.bulk.shared::cta.global.mbarrier::complete_tx::bytes [%0], [%1], %2, [%3];"
        :: "r"(dst), "l"(src), "r"(bytes), "r"(mbar) : "memory");
}
#define MBAR_INIT(a, n) asm volatile("mbarrier.init.shared.b64 [%0], %1;" :: "r"(a), "r"(n) : "memory")
#define MBAR_EXPECT_TX(a, tx) asm volatile("mbarrier.arrive.expect_tx.shared.b64 _, [%0], %1;" :: "r"(a), "r"(tx) : "memory")
__device__ __forceinline__ void mbar_wait(uint32_t addr, int phase) {
    asm volatile(
        "{\n\t.reg .pred P;\n\t"
        "W_%=:\n\t"
        "mbarrier.try_wait.parity.acquire.cta.shared::cta.b64 P, [%0], %1, 0x989680;\n\t"
        "@P bra.uni D_%=;\n\t"
        "bra.uni W_%=;\n\t"
        "D_%=:\n\t}"
        :: "r"(addr), "r"(phase) : "memory");
}
__device__ __forceinline__ void ldsm4(uint32_t* r, uint32_t a) {
    asm volatile("ldmatrix.sync.aligned.m8n8.x4.shared.b16 {%0,%1,%2,%3}, [%4];"
        : "=r"(r[0]), "=r"(r[1]), "=r"(r[2]), "=r"(r[3]) : "r"(a));
}
__device__ __forceinline__ void mma16816(float* d, const uint32_t* a, const uint32_t* b) {
    asm volatile(
        "mma.sync.aligned.m16n8k16.row.col.f32.f16.f16.f32 "
        "{%0,%1,%2,%3}, {%4,%5,%6,%7}, {%8,%9}, {%0,%1,%2,%3};"
        : "+f"(d[0]), "+f"(d[1]), "+f"(d[2]), "+f"(d[3])
        : "r"(a[0]), "r"(a[1]), "r"(a[2]), "r"(a[3]), "r"(b[0]), "r"(b[1]));
}

// ---------------------------------------------------------------------------
// convert: fp32 -> fp16 hi + lo, k-chunked layout with baked ldmatrix swizzle.
__global__ void __launch_bounds__(256) convert_kernel(const float4* __restrict__ ecg,
                                                      const float4* __restrict__ sent) {
    int n = blockIdx.x * 256 + threadIdx.x;     // 0..262143
    int kc = n >> 13;
    int r  = (n >> 1) & 4095;
    int s  = n & 1;
    int sw = s ^ ((r >> 2) & 1);
    size_t dst = (size_t)kc * 8192 + (size_t)r * 2 + sw;       // uint4 index
    size_t src = ((size_t)r * 512 + (size_t)kc * 16 + (size_t)s * 8) >> 2;  // float4 index

    float4 a0 = ecg[src], a1 = ecg[src + 1];
    uint4 h, l;
    {
        __half2 h2, l2;
        float2 f;
        f = make_float2(a0.x, a0.y); h2 = __float22half2_rn(f);
        l2 = __float22half2_rn(make_float2(f.x - __half2float(h2.x), f.y - __half2float(h2.y)));
        h.x = *(uint32_t*)&h2; l.x = *(uint32_t*)&l2;
        f = make_float2(a0.z, a0.w); h2 = __float22half2_rn(f);
        l2 = __float22half2_rn(make_float2(f.x - __half2float(h2.x), f.y - __half2float(h2.y)));
        h.y = *(uint32_t*)&h2; l.y = *(uint32_t*)&l2;
        f = make_float2(a1.x, a1.y); h2 = __float22half2_rn(f);
        l2 = __float22half2_rn(make_float2(f.x - __half2float(h2.x), f.y - __half2float(h2.y)));
        h.z = *(uint32_t*)&h2; l.z = *(uint32_t*)&l2;
        f = make_float2(a1.z, a1.w); h2 = __float22half2_rn(f);
        l2 = __float22half2_rn(make_float2(f.x - __half2float(h2.x), f.y - __half2float(h2.y)));
        h.w = *(uint32_t*)&h2; l.w = *(uint32_t*)&l2;
    }
    ((uint4*)eh_g)[dst] = h;
    ((uint4*)el_g)[dst] = l;

    float4 b0 = sent[src], b1 = sent[src + 1];
    {
        __half2 h2, l2;
        float2 f;
        f = make_float2(b0.x, b0.y); h2 = __float22half2_rn(f);
        l2 = __float22half2_rn(make_float2(f.x - __half2float(h2.x), f.y - __half2float(h2.y)));
        h.x = *(uint32_t*)&h2; l.x = *(uint32_t*)&l2;
        f = make_float2(b0.z, b0.w); h2 = __float22half2_rn(f);
        l2 = __float22half2_rn(make_float2(f.x - __half2float(h2.x), f.y - __half2float(h2.y)));
        h.y = *(uint32_t*)&h2; l.y = *(uint32_t*)&l2;
        f = make_float2(b1.x, b1.y); h2 = __float22half2_rn(f);
        l2 = __float22half2_rn(make_float2(f.x - __half2float(h2.x), f.y - __half2float(h2.y)));
        h.z = *(uint32_t*)&h2; l.z = *(uint32_t*)&l2;
        f = make_float2(b1.z, b1.w); h2 = __float22half2_rn(f);
        l2 = __float22half2_rn(make_float2(f.x - __half2float(h2.x), f.y - __half2float(h2.y)));
        h.w = *(uint32_t*)&h2; l.w = *(uint32_t*)&l2;
    }
    ((uint4*)sh_g)[dst] = h;
    ((uint4*)sl_g)[dst] = l;
}

// ---------------------------------------------------------------------------
__global__ void w1_kernel(const float* __restrict__ sent) {
    int row = blockIdx.x * 8 + (threadIdx.x >> 5);
    int lane = threadIdx.x & 31;
    const float* p = sent + (size_t)row * ND;
    float s = 0.f;
    #pragma unroll
    for (int d = lane; d < ND; d += 32) { float v = p[d]; s += v * v; }
    #pragma unroll
    for (int o = 16; o; o >>= 1) s += __shfl_xor_sync(0xffffffffu, s, o);
    if (lane == 0) w1g[row] = sqrtf(s);
}

// ---------------------------------------------------------------------------
// Gram: G_j = ecg_j @ ecg_j^T, output as fp16 hi/lo (row-major per j).
__global__ void __launch_bounds__(256) gram_kernel(const float* __restrict__ ecg) {
    __shared__ float tile[64][68];
    int j = blockIdx.x;
    int tid = threadIdx.x;
    int tx = tid & 15, ty = tid >> 4;
    const float* E = ecg + (size_t)j * NL * ND;

    float acc[4][4] = {};
    for (int kc = 0; kc < ND; kc += 64) {
        __syncthreads();
        for (int n = tid; n < 64 * 64; n += 256) {
            int r = n >> 6, d = n & 63;
            tile[d][r] = E[r * ND + kc + d];
        }
        __syncthreads();
        #pragma unroll 8
        for (int d = 0; d < 64; d++) {
            float4 a = *(const float4*)&tile[d][ty * 4];
            float4 b = *(const float4*)&tile[d][tx * 4];
            acc[0][0] += a.x * b.x; acc[0][1] += a.x * b.y; acc[0][2] += a.x * b.z; acc[0][3] += a.x * b.w;
            acc[1][0] += a.y * b.x; acc[1][1] += a.y * b.y; acc[1][2] += a.y * b.z; acc[1][3] += a.y * b.w;
            acc[2][0] += a.z * b.x; acc[2][1] += a.z * b.y; acc[2][2] += a.z * b.z; acc[2][3] += a.z * b.w;
            acc[3][0] += a.w * b.x; acc[3][1] += a.w * b.y; acc[3][2] += a.w * b.z; acc[3][3] += a.w * b.w;
        }
    }
    #pragma unroll
    for (int ss = 0; ss < 4; ss++)
        #pragma unroll
        for (int qq = 0; qq < 4; qq++) {
            float g = acc[ss][qq];
            __half gh = __float2half_rn(g);
            size_t idx = (size_t)j * 4096 + (ty * 4 + ss) * 64 + tx * 4 + qq;
            Ghg[idx] = gh;
            Glg[idx] = __float2half_rn(g - __half2float(gh));
        }
}

// ---------------------------------------------------------------------------
// pair_kernel: CTA = (bi, bj); 128 ecg rows x 128 sent rows. fp16x3 mma GEMM,
// 16 K=32 iterations, depth-2 32KB stages; S overlays stages; epilogue uses
// tensor cores for diag(A G A^T).
#define STAGE 32768
#define SROW 129
#define SBYTES (128 * SROW * 4)        // 66048 (> 2*STAGE)
#define AH_OFF 66048
#define AL_OFF 74240
#define BUFQ_OFF 82432
#define DSMEM_BYTES 98816

__global__ void __launch_bounds__(256, 2) pair_kernel(float* __restrict__ out) {
    extern __shared__ char dsm[];
    __shared__ uint64_t full_mb[2];
    __shared__ float w12s[64];
    __shared__ float w2sqs[64];
    __shared__ float ssum;

    uint32_t base = smem_u32(dsm);
    float* S    = (float*)dsm;                    // 128 x 129 fp32, overlays stages
    float* bufQ = (float*)(dsm + BUFQ_OFF);       // attn1 fp32
    uint32_t ahB = base + AH_OFF;
    uint32_t alB = base + AL_OFF;

    int tid = threadIdx.x;
    int wid = tid >> 5, lane = tid & 31;
    int bi = blockIdx.x, bj = blockIdx.y;
    int wm = wid & 1, wn = wid >> 1;

    const char* ehp = (const char*)eh_g;
    const char* elp = (const char*)el_g;
    const char* shp = (const char*)sh_g;
    const char* slp = (const char*)sl_g;
    size_t aoff = (size_t)bj * 4096;
    size_t boff = (size_t)bi * 4096;

    // ldmatrix lane offsets (swizzle baked in gmem: seg ^= (row>>2)&1, 32B rows)
    int q4 = lane >> 3;
    int ar = (lane & 7) + (q4 & 1) * 8;
    int aseg = q4 >> 1;
    uint32_t offA = (uint32_t)((wm * 64 + ar) * 32 + ((aseg ^ ((ar >> 2) & 1)) * 16));
    int br = (lane & 7) + ((q4 >> 1) & 1) * 8;
    int bs = q4 & 1;
    uint32_t offB = (uint32_t)((wn * 32 + br) * 32 + ((bs ^ ((br >> 2) & 1)) * 16));

    uint32_t mb[2];
    mb[0] = smem_u32(&full_mb[0]);
    mb[1] = smem_u32(&full_mb[1]);
    if (tid == 0) { MBAR_INIT(mb[0], 1); MBAR_INIT(mb[1], 1); }
    __syncthreads();

    // fill stage s with iteration it (k-chunks 2it, 2it+1)
    auto fill = [&](int s, int it) {
        uint32_t st = base + (uint32_t)s * STAGE;
        MBAR_EXPECT_TX(mb[s], STAGE);
        #pragma unroll
        for (int h = 0; h < 2; h++) {
            size_t blk = (size_t)(2 * it + h) * 131072;
            uint32_t hb = st + (uint32_t)h * 16384;
            bulk_cp(hb,          ehp + blk + aoff, 4096, mb[s]);
            bulk_cp(hb + 4096,   elp + blk + aoff, 4096, mb[s]);
            bulk_cp(hb + 8192,   shp + blk + boff, 4096, mb[s]);
            bulk_cp(hb + 12288,  slp + blk + boff, 4096, mb[s]);
        }
    };

    if (tid == 0) { fill(0, 0); fill(1, 1); }

    float acc[4][4][4] = {};

    for (int it = 0; it < 16; it++) {
        int s = it & 1;
        uint32_t st = base + (uint32_t)s * STAGE;
        mbar_wait(mb[s], (it >> 1) & 1);

        uint32_t af[4][4], al[4][4], bh[2][4], bl[2][4];
        // ---- half 0
        {
            uint32_t hb = st;
            ldsm4(bh[0], hb + 8192 + offB);
            ldsm4(bh[1], hb + 8192 + offB + 512);
            ldsm4(bl[0], hb + 12288 + offB);
            ldsm4(bl[1], hb + 12288 + offB + 512);
            #pragma unroll
            for (int f = 0; f < 4; f++) ldsm4(af[f], hb + offA + f * 512);
            #pragma unroll
            for (int f = 0; f < 4; f++) ldsm4(al[f], hb + 4096 + offA + f * 512);
            #pragma unroll
            for (int f = 0; f < 4; f++)
                #pragma unroll
                for (int g = 0; g < 4; g++) {
                    mma16816(acc[f][g], af[f], &bh[g >> 1][(g & 1) * 2]);
                    mma16816(acc[f][g], af[f], &bl[g >> 1][(g & 1) * 2]);
                    mma16816(acc[f][g], al[f], &bh[g >> 1][(g & 1) * 2]);
                }
        }
        // ---- half 1: ldsm, then barrier + refill, then mma
        {
            uint32_t hb = st + 16384;
            ldsm4(bh[0], hb + 8192 + offB);
            ldsm4(bh[1], hb + 8192 + offB + 512);
            ldsm4(bl[0], hb + 12288 + offB);
            ldsm4(bl[1], hb + 12288 + offB + 512);
            #pragma unroll
            for (int f = 0; f < 4; f++) ldsm4(af[f], hb + offA + f * 512);
            #pragma unroll
            for (int f = 0; f < 4; f++) ldsm4(al[f], hb + 4096 + offA + f * 512);

            __syncthreads();   // stage fully consumed
            if (tid == 0 && it + 2 < 16) fill(s, it + 2);

            #pragma unroll
            for (int f = 0; f < 4; f++)
                #pragma unroll
                for (int g = 0; g < 4; g++) {
                    mma16816(acc[f][g], af[f], &bh[g >> 1][(g & 1) * 2]);
                    mma16816(acc[f][g], af[f], &bl[g >> 1][(g & 1) * 2]);
                    mma16816(acc[f][g], al[f], &bh[g >> 1][(g & 1) * 2]);
                }
        }
    }
    __syncthreads();   // all mma issued; safe to overwrite stages with S

    // ---- write S (scores, fp32) to smem (overlays stage memory)
    {
        int r0 = lane >> 2, c0 = (lane & 3) * 2;
        #pragma unroll
        for (int f = 0; f < 4; f++)
            #pragma unroll
            for (int g = 0; g < 4; g++) {
                float* p = S + (size_t)(wm * 64 + f * 16 + r0) * SROW + wn * 32 + g * 8 + c0;
                p[0] = acc[f][g][0];
                p[1] = acc[f][g][1];
                p[8 * SROW] = acc[f][g][2];
                p[8 * SROW + 1] = acc[f][g][3];
            }
    }
    __syncthreads();

    // epilogue warp mapping for w2 mma: warp tile 16(m) x 32(n)
    int wm2 = wid & 3, wn2 = wid >> 2;
    int arow_e = wm2 * 16 + (lane & 7) + (q4 & 1) * 8;
    int aseg_e = q4 >> 1;

    // ---- epilogue: 4 (i,j) pairs
    for (int p = 0; p < 4; p++) {
        int jh = p >> 1, ih = p & 1;
        int i = 2 * bi + ih;
        int j = 2 * bj + jh;
        const float* Sp = S + (size_t)(64 * jh) * SROW + 64 * ih;  // S[s][q]

        if (tid < 64) w2sqs[tid] = 0.f;
        if (tid == 0) ssum = 0.f;
        __syncthreads();

        // softmax 1 over q (per row s): attn1[s][q] -> bufQ
        {
            int g = tid >> 2, l = tid & 3;
            float v[16];
            float mx = -1e30f;
            #pragma unroll
            for (int m = 0; m < 16; m++) { v[m] = Sp[g * SROW + l * 16 + m]; mx = fmaxf(mx, v[m]); }
            mx = fmaxf(mx, __shfl_xor_sync(0xffffffffu, mx, 1));
            mx = fmaxf(mx, __shfl_xor_sync(0xffffffffu, mx, 2));
            float sm = 0.f;
            #pragma unroll
            for (int m = 0; m < 16; m++) { v[m] = __expf(v[m] - mx); sm += v[m]; }
            sm += __shfl_xor_sync(0xffffffffu, sm, 1);
            sm += __shfl_xor_sync(0xffffffffu, sm, 2);
            float inv = 1.f / sm;
            #pragma unroll
            for (int m = 0; m < 16; m++) bufQ[g * 64 + l * 16 + m] = v[m] * inv;
        }
        __syncthreads();

        // softmax 2 over s (transposed): A[q][s] -> Ah/Al fp16 smem, plus w12
        {
            int q = tid >> 2, l = tid & 3;
            float e[16];
            float mx = -1e30f;
            #pragma unroll
            for (int m = 0; m < 16; m++) { e[m] = TEMP1 * bufQ[(l * 16 + m) * 64 + q]; mx = fmaxf(mx, e[m]); }
            mx = fmaxf(mx, __shfl_xor_sync(0xffffffffu, mx, 1));
            mx = fmaxf(mx, __shfl_xor_sync(0xffffffffu, mx, 2));
            float sm = 0.f;
            #pragma unroll
            for (int m = 0; m < 16; m++) { e[m] = __expf(e[m] - mx); sm += e[m]; }
            sm += __shfl_xor_sync(0xffffffffu, sm, 1);
            sm += __shfl_xor_sync(0xffffffffu, sm, 2);
            float invs = 1.f / sm;

            float w12p = 0.f;
            uint32_t hh[8], ll[8];
            #pragma unroll
            for (int m = 0; m < 16; m += 2) {
                int s0 = l * 16 + m;
                float a0 = e[m] * invs;
                float a1 = e[m + 1] * invs;
                w12p += a0 * Sp[s0 * SROW + q] + a1 * Sp[(s0 + 1) * SROW + q];
                __half2 h2 = __float22half2_rn(make_float2(a0, a1));
                __half2 l2 = __float22half2_rn(make_float2(a0 - __half2float(h2.x), a1 - __half2float(h2.y)));
                hh[m >> 1] = *(uint32_t*)&h2;
                ll[m >> 1] = *(uint32_t*)&l2;
                if (i == j) {
                    float* om = out + 1 + (size_t)i * NL * NL + q * 64 + s0;
                    om[0] = a0; om[1] = a1;
                }
            }
            #pragma unroll
            for (int h = 0; h < 2; h++) {
                uint32_t sgaddr = (uint32_t)(q * 128 + (((2 * l + h) ^ (q & 7)) << 4));
                *(uint4*)(dsm + AH_OFF + sgaddr) = make_uint4(hh[h*4], hh[h*4+1], hh[h*4+2], hh[h*4+3]);
                *(uint4*)(dsm + AL_OFF + sgaddr) = make_uint4(ll[h*4], ll[h*4+1], ll[h*4+2], ll[h*4+3]);
            }
            w12p += __shfl_xor_sync(0xffffffffu, w12p, 1);
            w12p += __shfl_xor_sync(0xffffffffu, w12p, 2);
            if (l == 0) w12s[q] = w12p;
        }
        __syncthreads();

        // ---- w2sq[q] = diag(A G A^T) via tensor cores (fp16x3)
        {
            const __half* Gh = Ghg + (size_t)j * 4096;
            const __half* Gl = Glg + (size_t)j * 4096;
            float md[4][4] = {};
            #pragma unroll
            for (int kk = 0; kk < 4; kk++) {
                int seg = 2 * kk + aseg_e;
                uint32_t aAddr = (uint32_t)(arow_e * 128 + ((seg ^ (arow_e & 7)) << 4));
                uint32_t ah4[4], al4[4];
                ldsm4(ah4, ahB + aAddr);
                ldsm4(al4, alB + aAddr);
                int k = kk * 16 + 2 * (lane & 3);
                #pragma unroll
                for (int nt = 0; nt < 4; nt++) {
                    int t = wn2 * 32 + nt * 8 + (lane >> 2);
                    uint32_t bhh[2], bll[2];
                    bhh[0] = *(const uint32_t*)(Gh + t * 64 + k);
                    bhh[1] = *(const uint32_t*)(Gh + t * 64 + k + 8);
                    bll[0] = *(const uint32_t*)(Gl + t * 64 + k);
                    bll[1] = *(const uint32_t*)(Gl + t * 64 + k + 8);
                    mma16816(md[nt], ah4, bhh);
                    mma16816(md[nt], ah4, bll);
                    mma16816(md[nt], al4, bhh);
                }
            }
            // diag: multiply by A[q][t] (reconstructed from hi+lo), reduce
            int q0 = wm2 * 16 + (lane >> 2);
            float p0 = 0.f, p1 = 0.f;
            #pragma unroll
            for (int nt = 0; nt < 4; nt++) {
                int t = wn2 * 32 + nt * 8 + 2 * (lane & 3);
                uint32_t off0 = (uint32_t)(q0 * 128 + (((t >> 3) ^ (q0 & 7)) << 4) + (t & 7) * 2);
                int q1 = q0 + 8;
                uint32_t off1 = (uint32_t)(q1 * 128 + (((t >> 3) ^ (q1 & 7)) << 4) + (t & 7) * 2);
                __half2 h0 = *(const __half2*)(dsm + AH_OFF + off0);
                __half2 l0 = *(const __half2*)(dsm + AL_OFF + off0);
                __half2 h1 = *(const __half2*)(dsm + AH_OFF + off1);
                __half2 l1 = *(const __half2*)(dsm + AL_OFF + off1);
                float2 a0 = __half22float2(h0), a0l = __half22float2(l0);
                float2 a1 = __half22float2(h1), a1l = __half22float2(l1);
                p0 += md[nt][0] * (a0.x + a0l.x) + md[nt][1] * (a0.y + a0l.y);
                p1 += md[nt][2] * (a1.x + a1l.x) + md[nt][3] * (a1.y + a1l.y);
            }
            p0 += __shfl_xor_sync(0xffffffffu, p0, 1);
            p0 += __shfl_xor_sync(0xffffffffu, p0, 2);
            p1 += __shfl_xor_sync(0xffffffffu, p1, 1);
            p1 += __shfl_xor_sync(0xffffffffu, p1, 2);
            if ((lane & 3) == 0) {
                atomicAdd(&w2sqs[q0], p0);
                atomicAdd(&w2sqs[q0 + 8], p1);
            }
        }
        __syncthreads();

        if (tid < 64) {
            int qv = tid;
            float w2 = sqrtf(w2sqs[qv]);
            float cosv = w12s[qv] / fmaxf(w1g[i * NL + qv] * w2, EPSV);
            atomicAdd(&ssum, __expf(TEMP2 * cosv));
        }
        __syncthreads();
        if (tid == 0) simg[j * NB + i] = TEMP3 * logf(ssum);
        __syncthreads();
    }
}

// ---------------------------------------------------------------------------
__global__ void __launch_bounds__(256) loss_kernel(float* __restrict__ out) {
    __shared__ float sm[64][65];
    __shared__ float acc;
    int t = threadIdx.x;
    if (t == 0) acc = 0.f;
    for (int n = t; n < 4096; n += 256) sm[n >> 6][n & 63] = simg[n];
    __syncthreads();
    int g = t >> 2, l = t & 3;
    float mx = -1e30f;
    #pragma unroll
    for (int m = 0; m < 16; m++) mx = fmaxf(mx, sm[g][l * 16 + m]);
    mx = fmaxf(mx, __shfl_xor_sync(0xffffffffu, mx, 1));
    mx = fmaxf(mx, __shfl_xor_sync(0xffffffffu, mx, 2));
    float s = 0.f;
    #pragma unroll
    for (int m = 0; m < 16; m++) s += expf(sm[g][l * 16 + m] - mx);
    s += __shfl_xor_sync(0xffffffffu, s, 1);
    s += __shfl_xor_sync(0xffffffffu, s, 2);
    float lp0 = sm[g][g] - mx - logf(s);

    float mc = -1e30f;
    #pragma unroll
    for (int m = 0; m < 16; m++) mc = fmaxf(mc, sm[l * 16 + m][g]);
    mc = fmaxf(mc, __shfl_xor_sync(0xffffffffu, mc, 1));
    mc = fmaxf(mc, __shfl_xor_sync(0xffffffffu, mc, 2));
    float sc = 0.f;
    #pragma unroll
    for (int m = 0; m < 16; m++) sc += expf(sm[l * 16 + m][g] - mc);
    sc += __shfl_xor_sync(0xffffffffu, sc, 1);
    sc += __shfl_xor_sync(0xffffffffu, sc, 2);
    float lp1 = sm[g][g] - mc - logf(sc);

    if (l == 0) atomicAdd(&acc, lp0 + lp1);
    __syncthreads();
    if (t == 0) out[0] = -acc / (2.0f * (float)NB);
}

// ---------------------------------------------------------------------------
extern "C" void kernel_launch(void* const* d_in, const int* in_sizes, int n_in,
                              void* d_out, int out_size) {
    const float* ecg = (const float*)d_in[0];
    const float* sent = (const float*)d_in[1];
    float* out = (float*)d_out;

    cudaFuncSetAttribute(pair_kernel, cudaFuncAttributeMaxDynamicSharedMemorySize, DSMEM_BYTES);

    convert_kernel<<<1024, 256>>>((const float4*)ecg, (const float4*)sent);
    w1_kernel<<<NB * NL / 8, 256>>>(sent);
    gram_kernel<<<NB, 256>>>(ecg);
    dim3 grid(32, 32);
    pair_kernel<<<grid, 256, DSMEM_BYTES>>>(out);
    loss_kernel<<<1, 256>>>(out);
}

// round 9
// speedup vs baseline: 1.2333x; 1.0123x over previous
#include <cuda_runtime.h>
#include <cuda_fp16.h>
#include <math.h>
#include <stdint.h>

#define NB 64
#define NL 64
#define ND 512
#define TEMP1 4.0f
#define TEMP2 5.0f
#define TEMP3 10.0f
#define EPSV 1e-8f

// ---------------- scratch (__device__ globals; no allocation allowed) -------
__device__ float w1g[NB * NL];
__device__ float simg[NB * NB];
__device__ __half Ghg[NB * 64 * 64];   // Gram hi fp16, row-major per j
__device__ __half Glg[NB * 64 * 64];   // Gram lo residual
// fp16 hi/lo splits, k-chunked + ldmatrix-swizzled: [kc(32)][row(4096)][16 halfs]
__device__ __align__(128) __half eh_g[32 * 4096 * 16];
__device__ __align__(128) __half el_g[32 * 4096 * 16];
__device__ __align__(128) __half sh_g[32 * 4096 * 16];
__device__ __align__(128) __half sl_g[32 * 4096 * 16];

// ---------------- PTX helpers (baseline ISA: sm_80/sm_90, no 'a' features) --
__device__ __forceinline__ uint32_t smem_u32(const void* p) {
    return (uint32_t)__cvta_generic_to_shared(p);
}
__device__ __forceinline__ void bulk_cp(uint32_t dst, const void* src, uint32_t bytes, uint32_t mbar) {
    asm volatile("cp.async.bulk.shared::cta.global.mbarrier::complete_tx::bytes [%0], [%1], %2, [%3];"
        :: "r"(dst), "l"(src), "r"(bytes), "r"(mbar) : "memory");
}
#define MBAR_INIT(a, n) asm volatile("mbarrier.init.shared.b64 [%0], %1;" :: "r"(a), "r"(n) : "memory")
#define MBAR_EXPECT_TX(a, tx) asm volatile("mbarrier.arrive.expect_tx.shared.b64 _, [%0], %1;" :: "r"(a), "r"(tx) : "memory")
#define MBAR_ARRIVE(a) asm volatile("mbarrier.arrive.shared.b64 _, [%0];" :: "r"(a) : "memory")
__device__ __forceinline__ void mbar_wait(uint32_t addr, int phase) {
    asm volatile(
        "{\n\t.reg .pred P;\n\t"
        "W_%=:\n\t"
        "mbarrier.try_wait.parity.acquire.cta.shared::cta.b64 P, [%0], %1, 0x989680;\n\t"
        "@P bra.uni D_%=;\n\t"
        "bra.uni W_%=;\n\t"
        "D_%=:\n\t}"
        :: "r"(addr), "r"(phase) : "memory");
}
__device__ __forceinline__ void ldsm4(uint32_t* r, uint32_t a) {
    asm volatile("ldmatrix.sync.aligned.m8n8.x4.shared.b16 {%0,%1,%2,%3}, [%4];"
        : "=r"(r[0]), "=r"(r[1]), "=r"(r[2]), "=r"(r[3]) : "r"(a));
}
__device__ __forceinline__ void mma16816(float* d, const uint32_t* a, const uint32_t* b) {
    asm volatile(
        "mma.sync.aligned.m16n8k16.row.col.f32.f16.f16.f32 "
        "{%0,%1,%2,%3}, {%4,%5,%6,%7}, {%8,%9}, {%0,%1,%2,%3};"
        : "+f"(d[0]), "+f"(d[1]), "+f"(d[2]), "+f"(d[3])
        : "r"(a[0]), "r"(a[1]), "r"(a[2]), "r"(a[3]), "r"(b[0]), "r"(b[1]));
}

// ---------------------------------------------------------------------------
// convert: fp32 -> fp16 hi + lo, k-chunked layout with baked ldmatrix swizzle.
__global__ void __launch_bounds__(256) convert_kernel(const float4* __restrict__ ecg,
                                                      const float4* __restrict__ sent) {
    int n = blockIdx.x * 256 + threadIdx.x;     // 0..262143
    int kc = n >> 13;
    int r  = (n >> 1) & 4095;
    int s  = n & 1;
    int sw = s ^ ((r >> 2) & 1);
    size_t dst = (size_t)kc * 8192 + (size_t)r * 2 + sw;       // uint4 index
    size_t src = ((size_t)r * 512 + (size_t)kc * 16 + (size_t)s * 8) >> 2;  // float4 index

    float4 a0 = ecg[src], a1 = ecg[src + 1];
    uint4 h, l;
    {
        __half2 h2, l2;
        float2 f;
        f = make_float2(a0.x, a0.y); h2 = __float22half2_rn(f);
        l2 = __float22half2_rn(make_float2(f.x - __half2float(h2.x), f.y - __half2float(h2.y)));
        h.x = *(uint32_t*)&h2; l.x = *(uint32_t*)&l2;
        f = make_float2(a0.z, a0.w); h2 = __float22half2_rn(f);
        l2 = __float22half2_rn(make_float2(f.x - __half2float(h2.x), f.y - __half2float(h2.y)));
        h.y = *(uint32_t*)&h2; l.y = *(uint32_t*)&l2;
        f = make_float2(a1.x, a1.y); h2 = __float22half2_rn(f);
        l2 = __float22half2_rn(make_float2(f.x - __half2float(h2.x), f.y - __half2float(h2.y)));
        h.z = *(uint32_t*)&h2; l.z = *(uint32_t*)&l2;
        f = make_float2(a1.z, a1.w); h2 = __float22half2_rn(f);
        l2 = __float22half2_rn(make_float2(f.x - __half2float(h2.x), f.y - __half2float(h2.y)));
        h.w = *(uint32_t*)&h2; l.w = *(uint32_t*)&l2;
    }
    ((uint4*)eh_g)[dst] = h;
    ((uint4*)el_g)[dst] = l;

    float4 b0 = sent[src], b1 = sent[src + 1];
    {
        __half2 h2, l2;
        float2 f;
        f = make_float2(b0.x, b0.y); h2 = __float22half2_rn(f);
        l2 = __float22half2_rn(make_float2(f.x - __half2float(h2.x), f.y - __half2float(h2.y)));
        h.x = *(uint32_t*)&h2; l.x = *(uint32_t*)&l2;
        f = make_float2(b0.z, b0.w); h2 = __float22half2_rn(f);
        l2 = __float22half2_rn(make_float2(f.x - __half2float(h2.x), f.y - __half2float(h2.y)));
        h.y = *(uint32_t*)&h2; l.y = *(uint32_t*)&l2;
        f = make_float2(b1.x, b1.y); h2 = __float22half2_rn(f);
        l2 = __float22half2_rn(make_float2(f.x - __half2float(h2.x), f.y - __half2float(h2.y)));
        h.z = *(uint32_t*)&h2; l.z = *(uint32_t*)&l2;
        f = make_float2(b1.z, b1.w); h2 = __float22half2_rn(f);
        l2 = __float22half2_rn(make_float2(f.x - __half2float(h2.x), f.y - __half2float(h2.y)));
        h.w = *(uint32_t*)&h2; l.w = *(uint32_t*)&l2;
    }
    ((uint4*)sh_g)[dst] = h;
    ((uint4*)sl_g)[dst] = l;
}

// ---------------------------------------------------------------------------
__global__ void w1_kernel(const float* __restrict__ sent) {
    int row = blockIdx.x * 8 + (threadIdx.x >> 5);
    int lane = threadIdx.x & 31;
    const float* p = sent + (size_t)row * ND;
    float s = 0.f;
    #pragma unroll
    for (int d = lane; d < ND; d += 32) { float v = p[d]; s += v * v; }
    #pragma unroll
    for (int o = 16; o; o >>= 1) s += __shfl_xor_sync(0xffffffffu, s, o);
    if (lane == 0) w1g[row] = sqrtf(s);
}

// ---------------------------------------------------------------------------
// Gram: G_j = ecg_j @ ecg_j^T, output as fp16 hi/lo (row-major per j).
__global__ void __launch_bounds__(256) gram_kernel(const float* __restrict__ ecg) {
    __shared__ float tile[64][68];
    int j = blockIdx.x;
    int tid = threadIdx.x;
    int tx = tid & 15, ty = tid >> 4;
    const float* E = ecg + (size_t)j * NL * ND;

    float acc[4][4] = {};
    for (int kc = 0; kc < ND; kc += 64) {
        __syncthreads();
        for (int n = tid; n < 64 * 64; n += 256) {
            int r = n >> 6, d = n & 63;
            tile[d][r] = E[r * ND + kc + d];
        }
        __syncthreads();
        #pragma unroll 8
        for (int d = 0; d < 64; d++) {
            float4 a = *(const float4*)&tile[d][ty * 4];
            float4 b = *(const float4*)&tile[d][tx * 4];
            acc[0][0] += a.x * b.x; acc[0][1] += a.x * b.y; acc[0][2] += a.x * b.z; acc[0][3] += a.x * b.w;
            acc[1][0] += a.y * b.x; acc[1][1] += a.y * b.y; acc[1][2] += a.y * b.z; acc[1][3] += a.y * b.w;
            acc[2][0] += a.z * b.x; acc[2][1] += a.z * b.y; acc[2][2] += a.z * b.z; acc[2][3] += a.z * b.w;
            acc[3][0] += a.w * b.x; acc[3][1] += a.w * b.y; acc[3][2] += a.w * b.z; acc[3][3] += a.w * b.w;
        }
    }
    #pragma unroll
    for (int ss = 0; ss < 4; ss++)
        #pragma unroll
        for (int qq = 0; qq < 4; qq++) {
            float g = acc[ss][qq];
            __half gh = __float2half_rn(g);
            size_t idx = (size_t)j * 4096 + (ty * 4 + ss) * 64 + tx * 4 + qq;
            Ghg[idx] = gh;
            Glg[idx] = __float2half_rn(g - __half2float(gh));
        }
}

// ---------------------------------------------------------------------------
// pair_kernel: CTA = (bi, bj); 128 ecg rows x 128 sent rows. fp16x3 mma GEMM.
// Free-running warps: full/consumed mbarrier pairs, no per-iter syncthreads.
#define STAGE 32768
#define SROW 129
#define SBYTES (128 * SROW * 4)        // 66048 (> 2*STAGE)
#define AH_OFF 66048
#define AL_OFF 74240
#define BUFQ_OFF 82432
#define DSMEM_BYTES 98816

__global__ void __launch_bounds__(256, 2) pair_kernel(float* __restrict__ out) {
    extern __shared__ char dsm[];
    __shared__ uint64_t full_mb[2];
    __shared__ uint64_t cons_mb[2];
    __shared__ float w12s[64];
    __shared__ float w2sqs[64];
    __shared__ float ssum;

    uint32_t base = smem_u32(dsm);
    float* S    = (float*)dsm;                    // 128 x 129 fp32, overlays stages
    float* bufQ = (float*)(dsm + BUFQ_OFF);       // attn1 fp32
    uint32_t ahB = base + AH_OFF;
    uint32_t alB = base + AL_OFF;

    int tid = threadIdx.x;
    int wid = tid >> 5, lane = tid & 31;
    int bi = blockIdx.x, bj = blockIdx.y;
    int wm = wid & 1, wn = wid >> 1;

    const char* ehp = (const char*)eh_g;
    const char* elp = (const char*)el_g;
    const char* shp = (const char*)sh_g;
    const char* slp = (const char*)sl_g;
    size_t aoff = (size_t)bj * 4096;
    size_t boff = (size_t)bi * 4096;

    // ldmatrix lane offsets (swizzle baked in gmem: seg ^= (row>>2)&1, 32B rows)
    int q4 = lane >> 3;
    int ar = (lane & 7) + (q4 & 1) * 8;
    int aseg = q4 >> 1;
    uint32_t offA = (uint32_t)((wm * 64 + ar) * 32 + ((aseg ^ ((ar >> 2) & 1)) * 16));
    int br = (lane & 7) + ((q4 >> 1) & 1) * 8;
    int bs = q4 & 1;
    uint32_t offB = (uint32_t)((wn * 32 + br) * 32 + ((bs ^ ((br >> 2) & 1)) * 16));

    uint32_t mb[2], cb[2];
    mb[0] = smem_u32(&full_mb[0]);
    mb[1] = smem_u32(&full_mb[1]);
    cb[0] = smem_u32(&cons_mb[0]);
    cb[1] = smem_u32(&cons_mb[1]);
    if (tid == 0) {
        MBAR_INIT(mb[0], 1); MBAR_INIT(mb[1], 1);
        MBAR_INIT(cb[0], 8); MBAR_INIT(cb[1], 8);
    }
    __syncthreads();

    // fill stage s with iteration it (k-chunks 2it, 2it+1)
    auto fill = [&](int s, int it) {
        uint32_t st = base + (uint32_t)s * STAGE;
        MBAR_EXPECT_TX(mb[s], STAGE);
        #pragma unroll
        for (int h = 0; h < 2; h++) {
            size_t blk = (size_t)(2 * it + h) * 131072;
            uint32_t hb = st + (uint32_t)h * 16384;
            bulk_cp(hb,          ehp + blk + aoff, 4096, mb[s]);
            bulk_cp(hb + 4096,   elp + blk + aoff, 4096, mb[s]);
            bulk_cp(hb + 8192,   shp + blk + boff, 4096, mb[s]);
            bulk_cp(hb + 12288,  slp + blk + boff, 4096, mb[s]);
        }
    };

    if (lane == 0 && wid < 2) fill(wid, wid);   // warp s seeds stage s

    float acc[4][4][4] = {};

    for (int it = 0; it < 16; it++) {
        int s = it & 1;
        uint32_t st = base + (uint32_t)s * STAGE;
        int ph = (it >> 1) & 1;
        mbar_wait(mb[s], ph);

        uint32_t af[4][4], al[4][4], bh[2][4], bl[2][4];
        // ---- half 0
        {
            uint32_t hb = st;
            ldsm4(bh[0], hb + 8192 + offB);
            ldsm4(bh[1], hb + 8192 + offB + 512);
            ldsm4(bl[0], hb + 12288 + offB);
            ldsm4(bl[1], hb + 12288 + offB + 512);
            #pragma unroll
            for (int f = 0; f < 4; f++) ldsm4(af[f], hb + offA + f * 512);
            #pragma unroll
            for (int f = 0; f < 4; f++) ldsm4(al[f], hb + 4096 + offA + f * 512);
            #pragma unroll
            for (int f = 0; f < 4; f++)
                #pragma unroll
                for (int g = 0; g < 4; g++) {
                    mma16816(acc[f][g], af[f], &bh[g >> 1][(g & 1) * 2]);
                    mma16816(acc[f][g], af[f], &bl[g >> 1][(g & 1) * 2]);
                    mma16816(acc[f][g], al[f], &bh[g >> 1][(g & 1) * 2]);
                }
        }
        // ---- half 1: ldsm, arrive consumed, mma, filler refills
        {
            uint32_t hb = st + 16384;
            ldsm4(bh[0], hb + 8192 + offB);
            ldsm4(bh[1], hb + 8192 + offB + 512);
            ldsm4(bl[0], hb + 12288 + offB);
            ldsm4(bl[1], hb + 12288 + offB + 512);
            #pragma unroll
            for (int f = 0; f < 4; f++) ldsm4(af[f], hb + offA + f * 512);
            #pragma unroll
            for (int f = 0; f < 4; f++) ldsm4(al[f], hb + 4096 + offA + f * 512);

            if (lane == 0) MBAR_ARRIVE(cb[s]);   // this warp done reading stage s

            #pragma unroll
            for (int f = 0; f < 4; f++)
                #pragma unroll
                for (int g = 0; g < 4; g++) {
                    mma16816(acc[f][g], af[f], &bh[g >> 1][(g & 1) * 2]);
                    mma16816(acc[f][g], af[f], &bl[g >> 1][(g & 1) * 2]);
                    mma16816(acc[f][g], al[f], &bh[g >> 1][(g & 1) * 2]);
                }

            if (wid == s && lane == 0 && it + 2 < 16) {
                mbar_wait(cb[s], ph);            // all 8 warps consumed stage s
                fill(s, it + 2);
            }
        }
    }
    __syncthreads();   // all warps past their last ldsm; safe to overwrite stages

    // ---- write S (scores, fp32) to smem (overlays stage memory)
    {
        int r0 = lane >> 2, c0 = (lane & 3) * 2;
        #pragma unroll
        for (int f = 0; f < 4; f++)
            #pragma unroll
            for (int g = 0; g < 4; g++) {
                float* p = S + (size_t)(wm * 64 + f * 16 + r0) * SROW + wn * 32 + g * 8 + c0;
                p[0] = acc[f][g][0];
                p[1] = acc[f][g][1];
                p[8 * SROW] = acc[f][g][2];
                p[8 * SROW + 1] = acc[f][g][3];
            }
    }
    __syncthreads();

    // epilogue warp mapping for w2 mma: warp tile 16(m) x 32(n)
    int wm2 = wid & 3, wn2 = wid >> 2;
    int arow_e = wm2 * 16 + (lane & 7) + (q4 & 1) * 8;
    int aseg_e = q4 >> 1;

    // ---- epilogue: 4 (i,j) pairs
    for (int p = 0; p < 4; p++) {
        int jh = p >> 1, ih = p & 1;
        int i = 2 * bi + ih;
        int j = 2 * bj + jh;
        const float* Sp = S + (size_t)(64 * jh) * SROW + 64 * ih;  // S[s][q]

        if (tid < 64) w2sqs[tid] = 0.f;
        if (tid == 0) ssum = 0.f;
        __syncthreads();

        // softmax 1 over q (per row s): attn1[s][q] -> bufQ
        {
            int g = tid >> 2, l = tid & 3;
            float v[16];
            float mx = -1e30f;
            #pragma unroll
            for (int m = 0; m < 16; m++) { v[m] = Sp[g * SROW + l * 16 + m]; mx = fmaxf(mx, v[m]); }
            mx = fmaxf(mx, __shfl_xor_sync(0xffffffffu, mx, 1));
            mx = fmaxf(mx, __shfl_xor_sync(0xffffffffu, mx, 2));
            float sm = 0.f;
            #pragma unroll
            for (int m = 0; m < 16; m++) { v[m] = __expf(v[m] - mx); sm += v[m]; }
            sm += __shfl_xor_sync(0xffffffffu, sm, 1);
            sm += __shfl_xor_sync(0xffffffffu, sm, 2);
            float inv = 1.f / sm;
            #pragma unroll
            for (int m = 0; m < 16; m++) bufQ[g * 64 + l * 16 + m] = v[m] * inv;
        }
        __syncthreads();

        // softmax 2 over s (transposed, no max shift: inputs in [0,4]): A[q][s]
        {
            int q = tid >> 2, l = tid & 3;
            float e[16];
            float sm = 0.f;
            #pragma unroll
            for (int m = 0; m < 16; m++) {
                e[m] = __expf(TEMP1 * bufQ[(l * 16 + m) * 64 + q]);
                sm += e[m];
            }
            sm += __shfl_xor_sync(0xffffffffu, sm, 1);
            sm += __shfl_xor_sync(0xffffffffu, sm, 2);
            float invs = 1.f / sm;

            float w12p = 0.f;
            uint32_t hh[8], ll[8];
            #pragma unroll
            for (int m = 0; m < 16; m += 2) {
                int s0 = l * 16 + m;
                float a0 = e[m] * invs;
                float a1 = e[m + 1] * invs;
                w12p += a0 * Sp[s0 * SROW + q] + a1 * Sp[(s0 + 1) * SROW + q];
                __half2 h2 = __float22half2_rn(make_float2(a0, a1));
                __half2 l2 = __float22half2_rn(make_float2(a0 - __half2float(h2.x), a1 - __half2float(h2.y)));
                hh[m >> 1] = *(uint32_t*)&h2;
                ll[m >> 1] = *(uint32_t*)&l2;
                if (i == j) {
                    float* om = out + 1 + (size_t)i * NL * NL + q * 64 + s0;
                    om[0] = a0; om[1] = a1;
                }
            }
            #pragma unroll
            for (int h = 0; h < 2; h++) {
                uint32_t sgaddr = (uint32_t)(q * 128 + (((2 * l + h) ^ (q & 7)) << 4));
                *(uint4*)(dsm + AH_OFF + sgaddr) = make_uint4(hh[h*4], hh[h*4+1], hh[h*4+2], hh[h*4+3]);
                *(uint4*)(dsm + AL_OFF + sgaddr) = make_uint4(ll[h*4], ll[h*4+1], ll[h*4+2], ll[h*4+3]);
            }
            w12p += __shfl_xor_sync(0xffffffffu, w12p, 1);
            w12p += __shfl_xor_sync(0xffffffffu, w12p, 2);
            if (l == 0) w12s[q] = w12p;
        }
        __syncthreads();

        // ---- w2sq[q] = diag(A G A^T) via tensor cores (fp16x3)
        {
            const __half* Gh = Ghg + (size_t)j * 4096;
            const __half* Gl = Glg + (size_t)j * 4096;
            float md[4][4] = {};
            #pragma unroll
            for (int kk = 0; kk < 4; kk++) {
                int seg = 2 * kk + aseg_e;
                uint32_t aAddr = (uint32_t)(arow_e * 128 + ((seg ^ (arow_e & 7)) << 4));
                uint32_t ah4[4], al4[4];
                ldsm4(ah4, ahB + aAddr);
                ldsm4(al4, alB + aAddr);
                int k = kk * 16 + 2 * (lane & 3);
                #pragma unroll
                for (int nt = 0; nt < 4; nt++) {
                    int t = wn2 * 32 + nt * 8 + (lane >> 2);
                    uint32_t bhh[2], bll[2];
                    bhh[0] = *(const uint32_t*)(Gh + t * 64 + k);
                    bhh[1] = *(const uint32_t*)(Gh + t * 64 + k + 8);
                    bll[0] = *(const uint32_t*)(Gl + t * 64 + k);
                    bll[1] = *(const uint32_t*)(Gl + t * 64 + k + 8);
                    mma16816(md[nt], ah4, bhh);
                    mma16816(md[nt], ah4, bll);
                    mma16816(md[nt], al4, bhh);
                }
            }
            // diag: multiply by A[q][t] (reconstructed from hi+lo), reduce
            int q0 = wm2 * 16 + (lane >> 2);
            float p0 = 0.f, p1 = 0.f;
            #pragma unroll
            for (int nt = 0; nt < 4; nt++) {
                int t = wn2 * 32 + nt * 8 + 2 * (lane & 3);
                uint32_t off0 = (uint32_t)(q0 * 128 + (((t >> 3) ^ (q0 & 7)) << 4) + (t & 7) * 2);
                int q1 = q0 + 8;
                uint32_t off1 = (uint32_t)(q1 * 128 + (((t >> 3) ^ (q1 & 7)) << 4) + (t & 7) * 2);
                __half2 h0 = *(const __half2*)(dsm + AH_OFF + off0);
                __half2 l0 = *(const __half2*)(dsm + AL_OFF + off0);
                __half2 h1 = *(const __half2*)(dsm + AH_OFF + off1);
                __half2 l1 = *(const __half2*)(dsm + AL_OFF + off1);
                float2 a0 = __half22float2(h0), a0l = __half22float2(l0);
                float2 a1 = __half22float2(h1), a1l = __half22float2(l1);
                p0 += md[nt][0] * (a0.x + a0l.x) + md[nt][1] * (a0.y + a0l.y);
                p1 += md[nt][2] * (a1.x + a1l.x) + md[nt][3] * (a1.y + a1l.y);
            }
            p0 += __shfl_xor_sync(0xffffffffu, p0, 1);
            p0 += __shfl_xor_sync(0xffffffffu, p0, 2);
            p1 += __shfl_xor_sync(0xffffffffu, p1, 1);
            p1 += __shfl_xor_sync(0xffffffffu, p1, 2);
            if ((lane & 3) == 0) {
                atomicAdd(&w2sqs[q0], p0);
                atomicAdd(&w2sqs[q0 + 8], p1);
            }
        }
        __syncthreads();

        if (tid < 64) {
            int qv = tid;
            float w2 = sqrtf(w2sqs[qv]);
            float cosv = w12s[qv] / fmaxf(w1g[i * NL + qv] * w2, EPSV);
            atomicAdd(&ssum, __expf(TEMP2 * cosv));
        }
        __syncthreads();
        if (tid == 0) simg[j * NB + i] = TEMP3 * logf(ssum);
        __syncthreads();
    }
}

// ---------------------------------------------------------------------------
__global__ void __launch_bounds__(256) loss_kernel(float* __restrict__ out) {
    __shared__ float sm[64][65];
    __shared__ float acc;
    int t = threadIdx.x;
    if (t == 0) acc = 0.f;
    for (int n = t; n < 4096; n += 256) sm[n >> 6][n & 63] = simg[n];
    __syncthreads();
    int g = t >> 2, l = t & 3;
    float mx = -1e30f;
    #pragma unroll
    for (int m = 0; m < 16; m++) mx = fmaxf(mx, sm[g][l * 16 + m]);
    mx = fmaxf(mx, __shfl_xor_sync(0xffffffffu, mx, 1));
    mx = fmaxf(mx, __shfl_xor_sync(0xffffffffu, mx, 2));
    float s = 0.f;
    #pragma unroll
    for (int m = 0; m < 16; m++) s += expf(sm[g][l * 16 + m] - mx);
    s += __shfl_xor_sync(0xffffffffu, s, 1);
    s += __shfl_xor_sync(0xffffffffu, s, 2);
    float lp0 = sm[g][g] - mx - logf(s);

    float mc = -1e30f;
    #pragma unroll
    for (int m = 0; m < 16; m++) mc = fmaxf(mc, sm[l * 16 + m][g]);
    mc = fmaxf(mc, __shfl_xor_sync(0xffffffffu, mc, 1));
    mc = fmaxf(mc, __shfl_xor_sync(0xffffffffu, mc, 2));
    float sc = 0.f;
    #pragma unroll
    for (int m = 0; m < 16; m++) sc += expf(sm[l * 16 + m][g] - mc);
    sc += __shfl_xor_sync(0xffffffffu, sc, 1);
    sc += __shfl_xor_sync(0xffffffffu, sc, 2);
    float lp1 = sm[g][g] - mc - logf(sc);

    if (l == 0) atomicAdd(&acc, lp0 + lp1);
    __syncthreads();
    if (t == 0) out[0] = -acc / (2.0f * (float)NB);
}

// ---------------------------------------------------------------------------
extern "C" void kernel_launch(void* const* d_in, const int* in_sizes, int n_in,
                              void* d_out, int out_size) {
    const float* ecg = (const float*)d_in[0];
    const float* sent = (const float*)d_in[1];
    float* out = (float*)d_out;

    cudaFuncSetAttribute(pair_kernel, cudaFuncAttributeMaxDynamicSharedMemorySize, DSMEM_BYTES);

    convert_kernel<<<1024, 256>>>((const float4*)ecg, (const float4*)sent);
    w1_kernel<<<NB * NL / 8, 256>>>(sent);
    gram_kernel<<<NB, 256>>>(ecg);
    dim3 grid(32, 32);
    pair_kernel<<<grid, 256, DSMEM_BYTES>>>(out);
    loss_kernel<<<1, 256>>>(out);
}

// round 14
// speedup vs baseline: 1.2912x; 1.0469x over previous
#include <cuda_runtime.h>
#include <cuda_fp16.h>
#include <math.h>
#include <stdint.h>

#define NB 64
#define NL 64
#define ND 512
#define TEMP1 4.0f
#define TEMP2 5.0f
#define TEMP3 10.0f
#define EPSV 1e-8f

// ---------------- scratch (__device__ globals; no allocation allowed) -------
__device__ float w1g[NB * NL];
__device__ float simg[NB * NB];
__device__ __half Ghg[NB * 64 * 64];   // Gram hi fp16, row-major per j
__device__ __half Glg[NB * 64 * 64];   // Gram lo residual
// fp16 hi/lo splits, k-chunked + ldmatrix-swizzled: [kc(32)][row(4096)][16 halfs]
__device__ __align__(128) __half eh_g[32 * 4096 * 16];
__device__ __align__(128) __half el_g[32 * 4096 * 16];
__device__ __align__(128) __half sh_g[32 * 4096 * 16];
__device__ __align__(128) __half sl_g[32 * 4096 * 16];

// ---------------- PTX helpers (baseline ISA: sm_80/sm_90, no 'a' features) --
__device__ __forceinline__ uint32_t smem_u32(const void* p) {
    return (uint32_t)__cvta_generic_to_shared(p);
}
__device__ __forceinline__ void bulk_cp(uint32_t dst, const void* src, uint32_t bytes, uint32_t mbar) {
    asm volatile("cp.async.bulk.shared::cta.global.mbarrier::complete_tx::bytes [%0], [%1], %2, [%3];"
        :: "r"(dst), "l"(src), "r"(bytes), "r"(mbar) : "memory");
}
#define MBAR_INIT(a, n) asm volatile("mbarrier.init.shared.b64 [%0], %1;" :: "r"(a), "r"(n) : "memory")
#define MBAR_EXPECT_TX(a, tx) asm volatile("mbarrier.arrive.expect_tx.shared.b64 _, [%0], %1;" :: "r"(a), "r"(tx) : "memory")
#define MBAR_ARRIVE(a) asm volatile("mbarrier.arrive.shared.b64 _, [%0];" :: "r"(a) : "memory")
__device__ __forceinline__ void mbar_wait(uint32_t addr, int phase) {
    asm volatile(
        "{\n\t.reg .pred P;\n\t"
        "W_%=:\n\t"
        "mbarrier.try_wait.parity.acquire.cta.shared::cta.b64 P, [%0], %1, 0x989680;\n\t"
        "@P bra.uni D_%=;\n\t"
        "bra.uni W_%=;\n\t"
        "D_%=:\n\t}"
        :: "r"(addr), "r"(phase) : "memory");
}
__device__ __forceinline__ void ldsm4(uint32_t* r, uint32_t a) {
    asm volatile("ldmatrix.sync.aligned.m8n8.x4.shared.b16 {%0,%1,%2,%3}, [%4];"
        : "=r"(r[0]), "=r"(r[1]), "=r"(r[2]), "=r"(r[3]) : "r"(a));
}
__device__ __forceinline__ void mma16816(float* d, const uint32_t* a, const uint32_t* b) {
    asm volatile(
        "mma.sync.aligned.m16n8k16.row.col.f32.f16.f16.f32 "
        "{%0,%1,%2,%3}, {%4,%5,%6,%7}, {%8,%9}, {%0,%1,%2,%3};"
        : "+f"(d[0]), "+f"(d[1]), "+f"(d[2]), "+f"(d[3])
        : "r"(a[0]), "r"(a[1]), "r"(a[2]), "r"(a[3]), "r"(b[0]), "r"(b[1]));
}

// ---------------------------------------------------------------------------
// convert: fp32 -> fp16 hi + lo, k-chunked layout with baked ldmatrix swizzle.
__global__ void __launch_bounds__(256) convert_kernel(const float4* __restrict__ ecg,
                                                      const float4* __restrict__ sent) {
    int n = blockIdx.x * 256 + threadIdx.x;     // 0..262143
    int kc = n >> 13;
    int r  = (n >> 1) & 4095;
    int s  = n & 1;
    int sw = s ^ ((r >> 2) & 1);
    size_t dst = (size_t)kc * 8192 + (size_t)r * 2 + sw;       // uint4 index
    size_t src = ((size_t)r * 512 + (size_t)kc * 16 + (size_t)s * 8) >> 2;  // float4 index

    float4 a0 = ecg[src], a1 = ecg[src + 1];
    uint4 h, l;
    {
        __half2 h2, l2;
        float2 f;
        f = make_float2(a0.x, a0.y); h2 = __float22half2_rn(f);
        l2 = __float22half2_rn(make_float2(f.x - __half2float(h2.x), f.y - __half2float(h2.y)));
        h.x = *(uint32_t*)&h2; l.x = *(uint32_t*)&l2;
        f = make_float2(a0.z, a0.w); h2 = __float22half2_rn(f);
        l2 = __float22half2_rn(make_float2(f.x - __half2float(h2.x), f.y - __half2float(h2.y)));
        h.y = *(uint32_t*)&h2; l.y = *(uint32_t*)&l2;
        f = make_float2(a1.x, a1.y); h2 = __float22half2_rn(f);
        l2 = __float22half2_rn(make_float2(f.x - __half2float(h2.x), f.y - __half2float(h2.y)));
        h.z = *(uint32_t*)&h2; l.z = *(uint32_t*)&l2;
        f = make_float2(a1.z, a1.w); h2 = __float22half2_rn(f);
        l2 = __float22half2_rn(make_float2(f.x - __half2float(h2.x), f.y - __half2float(h2.y)));
        h.w = *(uint32_t*)&h2; l.w = *(uint32_t*)&l2;
    }
    ((uint4*)eh_g)[dst] = h;
    ((uint4*)el_g)[dst] = l;

    float4 b0 = sent[src], b1 = sent[src + 1];
    {
        __half2 h2, l2;
        float2 f;
        f = make_float2(b0.x, b0.y); h2 = __float22half2_rn(f);
        l2 = __float22half2_rn(make_float2(f.x - __half2float(h2.x), f.y - __half2float(h2.y)));
        h.x = *(uint32_t*)&h2; l.x = *(uint32_t*)&l2;
        f = make_float2(b0.z, b0.w); h2 = __float22half2_rn(f);
        l2 = __float22half2_rn(make_float2(f.x - __half2float(h2.x), f.y - __half2float(h2.y)));
        h.y = *(uint32_t*)&h2; l.y = *(uint32_t*)&l2;
        f = make_float2(b1.x, b1.y); h2 = __float22half2_rn(f);
        l2 = __float22half2_rn(make_float2(f.x - __half2float(h2.x), f.y - __half2float(h2.y)));
        h.z = *(uint32_t*)&h2; l.z = *(uint32_t*)&l2;
        f = make_float2(b1.z, b1.w); h2 = __float22half2_rn(f);
        l2 = __float22half2_rn(make_float2(f.x - __half2float(h2.x), f.y - __half2float(h2.y)));
        h.w = *(uint32_t*)&h2; l.w = *(uint32_t*)&l2;
    }
    ((uint4*)sh_g)[dst] = h;
    ((uint4*)sl_g)[dst] = l;
}

// ---------------------------------------------------------------------------
__global__ void w1_kernel(const float* __restrict__ sent) {
    int row = blockIdx.x * 8 + (threadIdx.x >> 5);
    int lane = threadIdx.x & 31;
    const float* p = sent + (size_t)row * ND;
    float s = 0.f;
    #pragma unroll
    for (int d = lane; d < ND; d += 32) { float v = p[d]; s += v * v; }
    #pragma unroll
    for (int o = 16; o; o >>= 1) s += __shfl_xor_sync(0xffffffffu, s, o);
    if (lane == 0) w1g[row] = sqrtf(s);
}

// ---------------------------------------------------------------------------
// Gram: G_j = ecg_j @ ecg_j^T, output as fp16 hi/lo (row-major per j).
__global__ void __launch_bounds__(256) gram_kernel(const float* __restrict__ ecg) {
    __shared__ float tile[64][68];
    int j = blockIdx.x;
    int tid = threadIdx.x;
    int tx = tid & 15, ty = tid >> 4;
    const float* E = ecg + (size_t)j * NL * ND;

    float acc[4][4] = {};
    for (int kc = 0; kc < ND; kc += 64) {
        __syncthreads();
        for (int n = tid; n < 64 * 64; n += 256) {
            int r = n >> 6, d = n & 63;
            tile[d][r] = E[r * ND + kc + d];
        }
        __syncthreads();
        #pragma unroll 8
        for (int d = 0; d < 64; d++) {
            float4 a = *(const float4*)&tile[d][ty * 4];
            float4 b = *(const float4*)&tile[d][tx * 4];
            acc[0][0] += a.x * b.x; acc[0][1] += a.x * b.y; acc[0][2] += a.x * b.z; acc[0][3] += a.x * b.w;
            acc[1][0] += a.y * b.x; acc[1][1] += a.y * b.y; acc[1][2] += a.y * b.z; acc[1][3] += a.y * b.w;
            acc[2][0] += a.z * b.x; acc[2][1] += a.z * b.y; acc[2][2] += a.z * b.z; acc[2][3] += a.z * b.w;
            acc[3][0] += a.w * b.x; acc[3][1] += a.w * b.y; acc[3][2] += a.w * b.z; acc[3][3] += a.w * b.w;
        }
    }
    #pragma unroll
    for (int ss = 0; ss < 4; ss++)
        #pragma unroll
        for (int qq = 0; qq < 4; qq++) {
            float g = acc[ss][qq];
            __half gh = __float2half_rn(g);
            size_t idx = (size_t)j * 4096 + (ty * 4 + ss) * 64 + tx * 4 + qq;
            Ghg[idx] = gh;
            Glg[idx] = __float2half_rn(g - __half2float(gh));
        }
}

// ---------------------------------------------------------------------------
// pair_kernel: CTA = (bi, bj); 128 ecg rows x 128 sent rows. fp16x3 mma GEMM.
// Depth-3 32KB stage ring, free-running warps, full/consumed mbarrier pairs.
#define STAGE 32768
#define SROW 129
#define SBYTES (128 * SROW * 4)        // 66048
#define AH_OFF 66048
#define AL_OFF 74240
#define BUFQ_OFF 82432                 // bufQ: 64 x 65 fp32 = 16640
#define DSMEM_BYTES 99072

__global__ void __launch_bounds__(256, 2) pair_kernel(float* __restrict__ out) {
    extern __shared__ char dsm[];
    __shared__ uint64_t full_mb[3];
    __shared__ uint64_t cons_mb[3];
    __shared__ float w12s[64];
    __shared__ float w2sqs[64];
    __shared__ float ssum;

    uint32_t base = smem_u32(dsm);
    float* S    = (float*)dsm;                    // 128 x 129 fp32, overlays stages
    float* bufQ = (float*)(dsm + BUFQ_OFF);       // attn1 fp32, stride 65
    uint32_t ahB = base + AH_OFF;
    uint32_t alB = base + AL_OFF;

    int tid = threadIdx.x;
    int wid = tid >> 5, lane = tid & 31;
    int bi = blockIdx.x, bj = blockIdx.y;
    int wm = wid & 1, wn = wid >> 1;

    const char* ehp = (const char*)eh_g;
    const char* elp = (const char*)el_g;
    const char* shp = (const char*)sh_g;
    const char* slp = (const char*)sl_g;
    size_t aoff = (size_t)bj * 4096;
    size_t boff = (size_t)bi * 4096;

    // ldmatrix lane offsets (swizzle baked in gmem: seg ^= (row>>2)&1, 32B rows)
    int q4 = lane >> 3;
    int ar = (lane & 7) + (q4 & 1) * 8;
    int aseg = q4 >> 1;
    uint32_t offA = (uint32_t)((wm * 64 + ar) * 32 + ((aseg ^ ((ar >> 2) & 1)) * 16));
    int br = (lane & 7) + ((q4 >> 1) & 1) * 8;
    int bs = q4 & 1;
    uint32_t offB = (uint32_t)((wn * 32 + br) * 32 + ((bs ^ ((br >> 2) & 1)) * 16));

    uint32_t mb[3], cb[3];
    #pragma unroll
    for (int s = 0; s < 3; s++) {
        mb[s] = smem_u32(&full_mb[s]);
        cb[s] = smem_u32(&cons_mb[s]);
    }
    if (tid == 0) {
        #pragma unroll
        for (int s = 0; s < 3; s++) { MBAR_INIT(mb[s], 1); MBAR_INIT(cb[s], 8); }
    }
    __syncthreads();

    // fill stage s with iteration it (k-chunks 2it, 2it+1)
    auto fill = [&](int s, int it) {
        uint32_t st = base + (uint32_t)s * STAGE;
        MBAR_EXPECT_TX(mb[s], STAGE);
        #pragma unroll
        for (int h = 0; h < 2; h++) {
            size_t blk = (size_t)(2 * it + h) * 131072;
            uint32_t hb = st + (uint32_t)h * 16384;
            bulk_cp(hb,          ehp + blk + aoff, 4096, mb[s]);
            bulk_cp(hb + 4096,   elp + blk + aoff, 4096, mb[s]);
            bulk_cp(hb + 8192,   shp + blk + boff, 4096, mb[s]);
            bulk_cp(hb + 12288,  slp + blk + boff, 4096, mb[s]);
        }
    };

    if (lane == 0 && wid < 3) fill(wid, wid);   // warp s seeds stage s

    float acc[4][4][4] = {};

    for (int it = 0; it < 16; it++) {
        int s = it % 3;
        int ph = (it / 3) & 1;
        uint32_t st = base + (uint32_t)s * STAGE;
        mbar_wait(mb[s], ph);

        uint32_t af[4][4], al[4][4], bh[2][4], bl[2][4];
        // ---- half 0
        {
            uint32_t hb = st;
            ldsm4(bh[0], hb + 8192 + offB);
            ldsm4(bh[1], hb + 8192 + offB + 512);
            ldsm4(bl[0], hb + 12288 + offB);
            ldsm4(bl[1], hb + 12288 + offB + 512);
            #pragma unroll
            for (int f = 0; f < 4; f++) ldsm4(af[f], hb + offA + f * 512);
            #pragma unroll
            for (int f = 0; f < 4; f++) ldsm4(al[f], hb + 4096 + offA + f * 512);
            #pragma unroll
            for (int f = 0; f < 4; f++)
                #pragma unroll
                for (int g = 0; g < 4; g++) {
                    mma16816(acc[f][g], af[f], &bh[g >> 1][(g & 1) * 2]);
                    mma16816(acc[f][g], af[f], &bl[g >> 1][(g & 1) * 2]);
                    mma16816(acc[f][g], al[f], &bh[g >> 1][(g & 1) * 2]);
                }
        }
        // ---- half 1: ldsm, arrive consumed, mma, filler refills
        {
            uint32_t hb = st + 16384;
            ldsm4(bh[0], hb + 8192 + offB);
            ldsm4(bh[1], hb + 8192 + offB + 512);
            ldsm4(bl[0], hb + 12288 + offB);
            ldsm4(bl[1], hb + 12288 + offB + 512);
            #pragma unroll
            for (int f = 0; f < 4; f++) ldsm4(af[f], hb + offA + f * 512);
            #pragma unroll
            for (int f = 0; f < 4; f++) ldsm4(al[f], hb + 4096 + offA + f * 512);

            if (lane == 0) MBAR_ARRIVE(cb[s]);   // this warp done reading stage s

            #pragma unroll
            for (int f = 0; f < 4; f++)
                #pragma unroll
                for (int g = 0; g < 4; g++) {
                    mma16816(acc[f][g], af[f], &bh[g >> 1][(g & 1) * 2]);
                    mma16816(acc[f][g], af[f], &bl[g >> 1][(g & 1) * 2]);
                    mma16816(acc[f][g], al[f], &bh[g >> 1][(g & 1) * 2]);
                }

            if (wid == s && lane == 0 && it + 3 < 16) {
                mbar_wait(cb[s], ph);            // all 8 warps consumed stage s
                fill(s, it + 3);
            }
        }
    }
    __syncthreads();   // all warps past their last ldsm; safe to overwrite stages

    // ---- write S (scores, fp32) to smem (overlays stage memory)
    {
        int r0 = lane >> 2, c0 = (lane & 3) * 2;
        #pragma unroll
        for (int f = 0; f < 4; f++)
            #pragma unroll
            for (int g = 0; g < 4; g++) {
                float* p = S + (size_t)(wm * 64 + f * 16 + r0) * SROW + wn * 32 + g * 8 + c0;
                p[0] = acc[f][g][0];
                p[1] = acc[f][g][1];
                p[8 * SROW] = acc[f][g][2];
                p[8 * SROW + 1] = acc[f][g][3];
            }
    }
    __syncthreads();

    // epilogue warp mapping for w2 mma: warp tile 16(m) x 32(n)
    int wm2 = wid & 3, wn2 = wid >> 2;
    int arow_e = wm2 * 16 + (lane & 7) + (q4 & 1) * 8;
    int aseg_e = q4 >> 1;

    // ---- epilogue: 4 (i,j) pairs
    for (int p = 0; p < 4; p++) {
        int jh = p >> 1, ih = p & 1;
        int i = 2 * bi + ih;
        int j = 2 * bj + jh;
        const float* Sp = S + (size_t)(64 * jh) * SROW + 64 * ih;  // S[s][q]

        if (tid < 64) w2sqs[tid] = 0.f;
        if (tid == 0) ssum = 0.f;
        __syncthreads();

        // softmax 1 over q (per row s): attn1[s][q] -> bufQ (stride 65)
        {
            int g = tid >> 2, l = tid & 3;
            float v[16];
            float mx = -1e30f;
            #pragma unroll
            for (int m = 0; m < 16; m++) { v[m] = Sp[g * SROW + l * 16 + m]; mx = fmaxf(mx, v[m]); }
            mx = fmaxf(mx, __shfl_xor_sync(0xffffffffu, mx, 1));
            mx = fmaxf(mx, __shfl_xor_sync(0xffffffffu, mx, 2));
            float sm = 0.f;
            #pragma unroll
            for (int m = 0; m < 16; m++) { v[m] = __expf(v[m] - mx); sm += v[m]; }
            sm += __shfl_xor_sync(0xffffffffu, sm, 1);
            sm += __shfl_xor_sync(0xffffffffu, sm, 2);
            float inv = 1.f / sm;
            #pragma unroll
            for (int m = 0; m < 16; m++) bufQ[g * 65 + l * 16 + m] = v[m] * inv;
        }
        __syncthreads();

        // softmax 2 over s (transposed, no max shift: inputs in [0,4]): A[q][s]
        {
            int q = tid >> 2, l = tid & 3;
            float e[16];
            float sm = 0.f;
            #pragma unroll
            for (int m = 0; m < 16; m++) {
                e[m] = __expf(TEMP1 * bufQ[(l * 16 + m) * 65 + q]);
                sm += e[m];
            }
            sm += __shfl_xor_sync(0xffffffffu, sm, 1);
            sm += __shfl_xor_sync(0xffffffffu, sm, 2);
            float invs = 1.f / sm;

            float w12p = 0.f;
            uint32_t hh[8], ll[8];
            #pragma unroll
            for (int m = 0; m < 16; m += 2) {
                int s0 = l * 16 + m;
                float a0 = e[m] * invs;
                float a1 = e[m + 1] * invs;
                w12p += a0 * Sp[s0 * SROW + q] + a1 * Sp[(s0 + 1) * SROW + q];
                __half2 h2 = __float22half2_rn(make_float2(a0, a1));
                __half2 l2 = __float22half2_rn(make_float2(a0 - __half2float(h2.x), a1 - __half2float(h2.y)));
                hh[m >> 1] = *(uint32_t*)&h2;
                ll[m >> 1] = *(uint32_t*)&l2;
                if (i == j) {
                    float* om = out + 1 + (size_t)i * NL * NL + q * 64 + s0;
                    om[0] = a0; om[1] = a1;
                }
            }
            #pragma unroll
            for (int h = 0; h < 2; h++) {
                uint32_t sgaddr = (uint32_t)(q * 128 + (((2 * l + h) ^ (q & 7)) << 4));
                *(uint4*)(dsm + AH_OFF + sgaddr) = make_uint4(hh[h*4], hh[h*4+1], hh[h*4+2], hh[h*4+3]);
                *(uint4*)(dsm + AL_OFF + sgaddr) = make_uint4(ll[h*4], ll[h*4+1], ll[h*4+2], ll[h*4+3]);
            }
            w12p += __shfl_xor_sync(0xffffffffu, w12p, 1);
            w12p += __shfl_xor_sync(0xffffffffu, w12p, 2);
            if (l == 0) w12s[q] = w12p;
        }
        __syncthreads();

        // ---- w2sq[q] = diag(A G A^T) via tensor cores (fp16x3)
        {
            const __half* Gh = Ghg + (size_t)j * 4096;
            const __half* Gl = Glg + (size_t)j * 4096;
            float md[4][4] = {};
            #pragma unroll
            for (int kk = 0; kk < 4; kk++) {
                int seg = 2 * kk + aseg_e;
                uint32_t aAddr = (uint32_t)(arow_e * 128 + ((seg ^ (arow_e & 7)) << 4));
                uint32_t ah4[4], al4[4];
                ldsm4(ah4, ahB + aAddr);
                ldsm4(al4, alB + aAddr);
                int k = kk * 16 + 2 * (lane & 3);
                #pragma unroll
                for (int nt = 0; nt < 4; nt++) {
                    int t = wn2 * 32 + nt * 8 + (lane >> 2);
                    uint32_t bhh[2], bll[2];
                    bhh[0] = *(const uint32_t*)(Gh + t * 64 + k);
                    bhh[1] = *(const uint32_t*)(Gh + t * 64 + k + 8);
                    bll[0] = *(const uint32_t*)(Gl + t * 64 + k);
                    bll[1] = *(const uint32_t*)(Gl + t * 64 + k + 8);
                    mma16816(md[nt], ah4, bhh);
                    mma16816(md[nt], ah4, bll);
                    mma16816(md[nt], al4, bhh);
                }
            }
            // diag: multiply by A[q][t] (reconstructed from hi+lo), reduce
            int q0 = wm2 * 16 + (lane >> 2);
            float p0 = 0.f, p1 = 0.f;
            #pragma unroll
            for (int nt = 0; nt < 4; nt++) {
                int t = wn2 * 32 + nt * 8 + 2 * (lane & 3);
                uint32_t off0 = (uint32_t)(q0 * 128 + (((t >> 3) ^ (q0 & 7)) << 4) + (t & 7) * 2);
                int q1 = q0 + 8;
                uint32_t off1 = (uint32_t)(q1 * 128 + (((t >> 3) ^ (q1 & 7)) << 4) + (t & 7) * 2);
                __half2 h0 = *(const __half2*)(dsm + AH_OFF + off0);
                __half2 l0 = *(const __half2*)(dsm + AL_OFF + off0);
                __half2 h1 = *(const __half2*)(dsm + AH_OFF + off1);
                __half2 l1 = *(const __half2*)(dsm + AL_OFF + off1);
                float2 a0 = __half22float2(h0), a0l = __half22float2(l0);
                float2 a1 = __half22float2(h1), a1l = __half22float2(l1);
                p0 += md[nt][0] * (a0.x + a0l.x) + md[nt][1] * (a0.y + a0l.y);
                p1 += md[nt][2] * (a1.x + a1l.x) + md[nt][3] * (a1.y + a1l.y);
            }
            p0 += __shfl_xor_sync(0xffffffffu, p0, 1);
            p0 += __shfl_xor_sync(0xffffffffu, p0, 2);
            p1 += __shfl_xor_sync(0xffffffffu, p1, 1);
            p1 += __shfl_xor_sync(0xffffffffu, p1, 2);
            if ((lane & 3) == 0) {
                atomicAdd(&w2sqs[q0], p0);
                atomicAdd(&w2sqs[q0 + 8], p1);
            }
        }
        __syncthreads();

        if (tid < 64) {
            int qv = tid;
            float w2 = sqrtf(w2sqs[qv]);
            float cosv = w12s[qv] / fmaxf(w1g[i * NL + qv] * w2, EPSV);
            atomicAdd(&ssum, __expf(TEMP2 * cosv));
        }
        __syncthreads();
        if (tid == 0) simg[j * NB + i] = TEMP3 * logf(ssum);
        __syncthreads();
    }
}

// ---------------------------------------------------------------------------
__global__ void __launch_bounds__(256) loss_kernel(float* __restrict__ out) {
    __shared__ float sm[64][65];
    __shared__ float acc;
    int t = threadIdx.x;
    if (t == 0) acc = 0.f;
    for (int n = t; n < 4096; n += 256) sm[n >> 6][n & 63] = simg[n];
    __syncthreads();
    int g = t >> 2, l = t & 3;
    float mx = -1e30f;
    #pragma unroll
    for (int m = 0; m < 16; m++) mx = fmaxf(mx, sm[g][l * 16 + m]);
    mx = fmaxf(mx, __shfl_xor_sync(0xffffffffu, mx, 1));
    mx = fmaxf(mx, __shfl_xor_sync(0xffffffffu, mx, 2));
    float s = 0.f;
    #pragma unroll
    for (int m = 0; m < 16; m++) s += expf(sm[g][l * 16 + m] - mx);
    s += __shfl_xor_sync(0xffffffffu, s, 1);
    s += __shfl_xor_sync(0xffffffffu, s, 2);
    float lp0 = sm[g][g] - mx - logf(s);

    float mc = -1e30f;
    #pragma unroll
    for (int m = 0; m < 16; m++) mc = fmaxf(mc, sm[l * 16 + m][g]);
    mc = fmaxf(mc, __shfl_xor_sync(0xffffffffu, mc, 1));
    mc = fmaxf(mc, __shfl_xor_sync(0xffffffffu, mc, 2));
    float sc = 0.f;
    #pragma unroll
    for (int m = 0; m < 16; m++) sc += expf(sm[l * 16 + m][g] - mc);
    sc += __shfl_xor_sync(0xffffffffu, sc, 1);
    sc += __shfl_xor_sync(0xffffffffu, sc, 2);
    float lp1 = sm[g][g] - mc - logf(sc);

    if (l == 0) atomicAdd(&acc, lp0 + lp1);
    __syncthreads();
    if (t == 0) out[0] = -acc / (2.0f * (float)NB);
}

// ---------------------------------------------------------------------------
extern "C" void kernel_launch(void* const* d_in, const int* in_sizes, int n_in,
                              void* d_out, int out_size) {
    const float* ecg = (const float*)d_in[0];
    const float* sent = (const float*)d_in[1];
    float* out = (float*)d_out;

    cudaFuncSetAttribute(pair_kernel, cudaFuncAttributeMaxDynamicSharedMemorySize, DSMEM_BYTES);

    convert_kernel<<<1024, 256>>>((const float4*)ecg, (const float4*)sent);
    w1_kernel<<<NB * NL / 8, 256>>>(sent);
    gram_kernel<<<NB, 256>>>(ecg);
    dim3 grid(32, 32);
    pair_kernel<<<grid, 256, DSMEM_BYTES>>>(out);
    loss_kernel<<<1, 256>>>(out);
}